// round 1
// baseline (speedup 1.0000x reference)
#include <cuda_runtime.h>
#include <cuda_bf16.h>
#include <math.h>

// Problem constants
#define NK    8192        // num_embeddings
#define DD    256         // embedding_dim
#define NB    8
#define NH    64
#define NW    64
#define NTOK  32768       // B*H*W
#define HWSZ  4096        // H*W
#define ZELEMS 8388608    // B*D*H*W

// Output layout offsets (all float32, concatenated in reference return order)
#define OFF_ZST  0
#define OFF_IDX  8388608
#define OFF_ZQ   8421376
#define OFF_EMB  16809984
#define OFF_CS   18907136
#define OFF_AVG  18915328

// Scratch (allocation-free: __device__ globals)
__device__ float g_eN[NK * DD];    // normalized embedding, row-major
__device__ int   g_idx[NTOK];      // argmax code per token

// ---------------------------------------------------------------------------
// init: new_cluster_size = 0.99*cluster_size ; new_embed_avg = 0.99*embed_avg
// (scatter kernel later atomically adds the 0.01*counts / 0.01*embed_sum part)
// ---------------------------------------------------------------------------
__global__ void init_kernel(const float* __restrict__ cluster_size,
                            const float* __restrict__ embed_avg,
                            float* __restrict__ cs_out,
                            float* __restrict__ avg_out) {
    int t = blockIdx.x * blockDim.x + threadIdx.x;
    if (t < NK) cs_out[t] = 0.99f * cluster_size[t];
    if (t < NK * DD) avg_out[t] = 0.99f * embed_avg[t];
}

// ---------------------------------------------------------------------------
// Row L2-normalize: out[r] = in[r] / max(||in[r]||, 1e-12). One warp per row.
// ---------------------------------------------------------------------------
__global__ void norm_rows_kernel(const float* __restrict__ in,
                                 float* __restrict__ out, int nrows) {
    int warp = (blockIdx.x * blockDim.x + threadIdx.x) >> 5;
    int lane = threadIdx.x & 31;
    if (warp >= nrows) return;
    const float4* ip = reinterpret_cast<const float4*>(in + (size_t)warp * DD);
    float4 v0 = ip[lane];
    float4 v1 = ip[lane + 32];
    float s = v0.x * v0.x + v0.y * v0.y + v0.z * v0.z + v0.w * v0.w
            + v1.x * v1.x + v1.y * v1.y + v1.z * v1.z + v1.w * v1.w;
    #pragma unroll
    for (int off = 16; off > 0; off >>= 1)
        s += __shfl_xor_sync(0xFFFFFFFFu, s, off);
    float nrm = fmaxf(sqrtf(s), 1e-12f);
    float4 o0, o1;
    o0.x = v0.x / nrm; o0.y = v0.y / nrm; o0.z = v0.z / nrm; o0.w = v0.w / nrm;
    o1.x = v1.x / nrm; o1.y = v1.y / nrm; o1.z = v1.z / nrm; o1.w = v1.w / nrm;
    float4* op = reinterpret_cast<float4*>(out + (size_t)warp * DD);
    op[lane] = o0;
    op[lane + 32] = o1;
}

// ---------------------------------------------------------------------------
// Fused sim-GEMM + argmax.
// A = flat_z (N x D), viewed directly from z (B,D,H,W): for a row block that
// stays within one b (128 | 4096 guarantees it), A[m][d] = zb[d*4096 + m],
// i.e. already "transposed" for coalesced As[k][m] loads.
// B = g_eN (K x D) row-major, transposed into Bs on load.
// Each block: 128 rows, loops over all 8192 codes in 128-wide tiles,
// full D=256 accumulation in fp32, then running (max, first-idx) per row.
// ---------------------------------------------------------------------------
#define BM 128
#define BN 128
#define BKD 16
#define BNP 132   // padded Bs stride

__global__ __launch_bounds__(256) void gemm_argmax_kernel(const float* __restrict__ z) {
    __shared__ float As[BKD][BM];
    __shared__ float Bs[BKD][BNP];

    int tid = threadIdx.x;
    int tx = tid & 15;        // col group (8 cols each)
    int ty = tid >> 4;        // row group (8 rows each)
    int rowBase = blockIdx.x * BM;
    int b  = rowBase >> 12;
    int hw = rowBase & (HWSZ - 1);
    const float* zb = z + (size_t)b * DD * HWSZ + hw;   // (d,m) -> zb[d*4096+m]

    float bestV[8];
    int   bestI[8];
    #pragma unroll
    for (int i = 0; i < 8; i++) { bestV[i] = -1e30f; bestI[i] = 0; }

    for (int k0 = 0; k0 < NK; k0 += BN) {
        float acc[8][8];
        #pragma unroll
        for (int i = 0; i < 8; i++)
            #pragma unroll
            for (int j = 0; j < 8; j++) acc[i][j] = 0.0f;

        for (int d0 = 0; d0 < DD; d0 += BKD) {
            __syncthreads();
            // Load A tile (2048 floats), coalesced along m
            #pragma unroll
            for (int i = 0; i < 8; i++) {
                int lin = tid + i * 256;
                int dk = lin >> 7, m = lin & 127;
                As[dk][m] = zb[(d0 + dk) * HWSZ + m];
            }
            // Load B tile (2048 floats), transpose into Bs[dk][kn]
            #pragma unroll
            for (int i = 0; i < 8; i++) {
                int lin = tid + i * 256;
                int kn = lin >> 4, dk = lin & 15;
                Bs[dk][kn] = g_eN[(size_t)(k0 + kn) * DD + d0 + dk];
            }
            __syncthreads();
            #pragma unroll
            for (int dk = 0; dk < BKD; dk++) {
                float a[8], bb[8];
                #pragma unroll
                for (int i = 0; i < 8; i++) a[i] = As[dk][ty * 8 + i];
                #pragma unroll
                for (int j = 0; j < 8; j++) bb[j] = Bs[dk][tx * 8 + j];
                #pragma unroll
                for (int i = 0; i < 8; i++)
                    #pragma unroll
                    for (int j = 0; j < 8; j++)
                        acc[i][j] = fmaf(a[i], bb[j], acc[i][j]);
            }
        }
        // Update running argmax (strict > keeps first occurrence; j ascending,
        // k0 ascending => per-thread candidate order is ascending idx)
        #pragma unroll
        for (int i = 0; i < 8; i++) {
            #pragma unroll
            for (int j = 0; j < 8; j++) {
                float v = acc[i][j];
                if (v > bestV[i]) { bestV[i] = v; bestI[i] = k0 + tx * 8 + j; }
            }
        }
    }

    // Cross-thread reduction: 16 threads (tx) per row
    __syncthreads();
    float* sv = &As[0][0];            // 128*16 floats = 8KB (fits As)
    int*   si = reinterpret_cast<int*>(&Bs[0][0]);
    #pragma unroll
    for (int i = 0; i < 8; i++) {
        int m = ty * 8 + i;
        sv[m * 16 + tx] = bestV[i];
        si[m * 16 + tx] = bestI[i];
    }
    __syncthreads();
    if (tid < 128) {
        int m = tid;
        float bv = sv[m * 16];
        int   bi = si[m * 16];
        #pragma unroll
        for (int t = 1; t < 16; t++) {
            float v = sv[m * 16 + t];
            int  id = si[m * 16 + t];
            if (v > bv || (v == bv && id < bi)) { bv = v; bi = id; }
        }
        g_idx[rowBase + m] = bi;
    }
}

// ---------------------------------------------------------------------------
// EMA scatter: avg_out[idx[n]][d] += 0.01*z[n][d] ; cs_out[idx[n]] += 0.01
// Thread per z element; coalesced z reads; spread float atomics to L2.
// ---------------------------------------------------------------------------
__global__ void scatter_kernel(const float* __restrict__ z,
                               float* __restrict__ avg_out,
                               float* __restrict__ cs_out) {
    int t = blockIdx.x * blockDim.x + threadIdx.x;
    if (t >= ZELEMS) return;
    int hw = t & (HWSZ - 1);
    int bd = t >> 12;
    int d  = bd & (DD - 1);
    int b  = bd >> 8;
    int n  = (b << 12) | hw;
    int id = __ldg(&g_idx[n]);
    float v = z[t];
    atomicAdd(&avg_out[id * DD + d], 0.01f * v);
    if (d == 0) atomicAdd(&cs_out[id], 0.01f);
}

// ---------------------------------------------------------------------------
// Output gather: z_q[t] = embedding[idx[n]][d] (raw embedding),
// z_q_st[t] = z + (z_q - z) literally, idx written as float.
// Coalesced writes; embedding gather served from L2 (8MB resident).
// ---------------------------------------------------------------------------
__global__ void output_kernel(const float* __restrict__ z,
                              const float* __restrict__ embedding,
                              float* __restrict__ zst,
                              float* __restrict__ zq,
                              float* __restrict__ idxf) {
    int t = blockIdx.x * blockDim.x + threadIdx.x;
    if (t < NTOK) idxf[t] = (float)g_idx[t];
    if (t >= ZELEMS) return;
    int hw = t & (HWSZ - 1);
    int bd = t >> 12;
    int d  = bd & (DD - 1);
    int b  = bd >> 8;
    int n  = (b << 12) | hw;
    int id = __ldg(&g_idx[n]);
    float e  = __ldg(&embedding[id * DD + d]);
    float zv = z[t];
    zq[t]  = e;
    zst[t] = zv + (e - zv);
}

// ---------------------------------------------------------------------------
extern "C" void kernel_launch(void* const* d_in, const int* in_sizes, int n_in,
                              void* d_out, int out_size) {
    const float* z            = (const float*)d_in[0];
    const float* embedding    = (const float*)d_in[1];
    const float* cluster_size = (const float*)d_in[2];
    const float* embed_avg    = (const float*)d_in[3];

    float* out     = (float*)d_out;
    float* zst_o   = out + OFF_ZST;
    float* idx_o   = out + OFF_IDX;
    float* zq_o    = out + OFF_ZQ;
    float* emb_o   = out + OFF_EMB;
    float* cs_o    = out + OFF_CS;
    float* avg_o   = out + OFF_AVG;

    // Resolve device-symbol addresses for kernels that take them as args
    // (kernels reference g_eN / g_idx directly; nothing to resolve here)

    init_kernel<<<(NK * DD + 255) / 256, 256>>>(cluster_size, embed_avg, cs_o, avg_o);

    // normalized codebook (argmax uses it; gather uses raw embedding)
    float* eN_ptr;
    cudaGetSymbolAddress((void**)&eN_ptr, g_eN);
    norm_rows_kernel<<<NK / 8, 256>>>(embedding, eN_ptr, NK);

    gemm_argmax_kernel<<<NTOK / BM, 256>>>(z);

    scatter_kernel<<<ZELEMS / 256, 256>>>(z, avg_o, cs_o);

    output_kernel<<<ZELEMS / 256, 256>>>(z, embedding, zst_o, zq_o, idx_o);

    // new_embedding = l2norm(new_embed_avg / cs) == l2norm(new_embed_avg)
    norm_rows_kernel<<<NK / 8, 256>>>(avg_o, emb_o, NK);
}

// round 3
// speedup vs baseline: 1.8577x; 1.8577x over previous
#include <cuda_runtime.h>
#include <cuda_bf16.h>
#include <math.h>
#include <stdint.h>

// Problem constants
#define NK    8192        // num_embeddings
#define DD    256         // embedding_dim
#define NTOK  32768       // B*H*W
#define HWSZ  4096        // H*W
#define ZELEMS 8388608    // B*D*H*W

// Output layout offsets (float32, reference return order)
#define OFF_ZST  0
#define OFF_IDX  8388608
#define OFF_ZQ   8421376
#define OFF_EMB  16809984
#define OFF_CS   18907136
#define OFF_AVG  18915328

// K-slicing for wave balance
#define NSLICE 8
#define KSLICE 1024       // NK / NSLICE
#define NTILE  256        // NTOK / 128

// Scratch (__device__ globals: allocation-free)
__device__ float g_Ahi[NTOK * DD];   // token-major z, tf32 hi
__device__ float g_Alo[NTOK * DD];   // token-major z, tf32 lo
__device__ float g_Bhi[NK * DD];     // normalized codebook, tf32 hi
__device__ float g_Blo[NK * DD];     // normalized codebook, tf32 lo
__device__ float g_pv[NTILE * NSLICE * 128];  // per (tile,slice) best value
__device__ int   g_pi[NTILE * NSLICE * 128];  // per (tile,slice) best index
__device__ int   g_idx[NTOK];

// ============================================================================
// helpers
// ============================================================================
__device__ __forceinline__ uint32_t smem_to_u32(const void* p) {
    uint32_t a;
    asm("{ .reg .u64 t; cvta.to.shared.u64 t, %1; cvt.u32.u64 %0, t; }" : "=r"(a) : "l"(p));
    return a;
}
__device__ __forceinline__ void cpasync16(uint32_t dst, const void* src) {
    asm volatile("cp.async.cg.shared.global [%0], [%1], 16;" :: "r"(dst), "l"(src));
}
#define CPASYNC_COMMIT() asm volatile("cp.async.commit_group;" ::: "memory")
#define CPASYNC_WAIT(n)  asm volatile("cp.async.wait_group %0;" :: "n"(n) : "memory")

__device__ __forceinline__ float tf32_rna(float x) {
    uint32_t u;
    asm("cvt.rna.tf32.f32 %0, %1;" : "=r"(u) : "f"(x));
    return __uint_as_float(u);
}

// m16n8k8 tf32 mma: D += A*B  (A row-major 16x8, B col-major 8x8 stored n-major)
__device__ __forceinline__ void mma8(float* c, const float* a, const float* b) {
    asm volatile(
        "mma.sync.aligned.m16n8k8.row.col.f32.tf32.tf32.f32 "
        "{%0,%1,%2,%3}, {%4,%5,%6,%7}, {%8,%9}, {%0,%1,%2,%3};"
        : "+f"(c[0]), "+f"(c[1]), "+f"(c[2]), "+f"(c[3])
        : "r"(__float_as_uint(a[0])), "r"(__float_as_uint(a[1])),
          "r"(__float_as_uint(a[2])), "r"(__float_as_uint(a[3])),
          "r"(__float_as_uint(b[0])), "r"(__float_as_uint(b[1])));
}

// ============================================================================
// init: new_cluster_size = 0.99*cs ; new_embed_avg = 0.99*embed_avg
// ============================================================================
__global__ void init_kernel(const float* __restrict__ cluster_size,
                            const float* __restrict__ embed_avg,
                            float* __restrict__ cs_out,
                            float* __restrict__ avg_out) {
    int t = blockIdx.x * blockDim.x + threadIdx.x;
    if (t < NK) cs_out[t] = 0.99f * cluster_size[t];
    if (t < NK * DD) avg_out[t] = 0.99f * embed_avg[t];
}

// ============================================================================
// Row L2-normalize (final new_embedding). One warp per row.
// ============================================================================
__global__ void norm_rows_kernel(const float* __restrict__ in,
                                 float* __restrict__ out, int nrows) {
    int warp = (blockIdx.x * blockDim.x + threadIdx.x) >> 5;
    int lane = threadIdx.x & 31;
    if (warp >= nrows) return;
    const float4* ip = reinterpret_cast<const float4*>(in + (size_t)warp * DD);
    float4 v0 = ip[lane];
    float4 v1 = ip[lane + 32];
    float s = v0.x*v0.x + v0.y*v0.y + v0.z*v0.z + v0.w*v0.w
            + v1.x*v1.x + v1.y*v1.y + v1.z*v1.z + v1.w*v1.w;
    #pragma unroll
    for (int off = 16; off > 0; off >>= 1) s += __shfl_xor_sync(0xFFFFFFFFu, s, off);
    float nrm = fmaxf(sqrtf(s), 1e-12f);
    float4 o0, o1;
    o0.x = v0.x/nrm; o0.y = v0.y/nrm; o0.z = v0.z/nrm; o0.w = v0.w/nrm;
    o1.x = v1.x/nrm; o1.y = v1.y/nrm; o1.z = v1.z/nrm; o1.w = v1.w/nrm;
    float4* op = reinterpret_cast<float4*>(out + (size_t)warp * DD);
    op[lane] = o0; op[lane + 32] = o1;
}

// ============================================================================
// normalize codebook rows + tf32 hi/lo split -> g_Bhi/g_Blo. Warp per row.
// ============================================================================
__global__ void norm_split_embed(const float* __restrict__ in) {
    int warp = (blockIdx.x * blockDim.x + threadIdx.x) >> 5;
    int lane = threadIdx.x & 31;
    if (warp >= NK) return;
    const float4* ip = reinterpret_cast<const float4*>(in + (size_t)warp * DD);
    float4 v0 = ip[lane];
    float4 v1 = ip[lane + 32];
    float s = v0.x*v0.x + v0.y*v0.y + v0.z*v0.z + v0.w*v0.w
            + v1.x*v1.x + v1.y*v1.y + v1.z*v1.z + v1.w*v1.w;
    #pragma unroll
    for (int off = 16; off > 0; off >>= 1) s += __shfl_xor_sync(0xFFFFFFFFu, s, off);
    float inv = 1.0f / fmaxf(sqrtf(s), 1e-12f);
    float vv[8] = {v0.x, v0.y, v0.z, v0.w, v1.x, v1.y, v1.z, v1.w};
    float hi[8], lo[8];
    #pragma unroll
    for (int i = 0; i < 8; i++) {
        float v = vv[i] * inv;
        hi[i] = tf32_rna(v);
        lo[i] = tf32_rna(v - hi[i]);
    }
    float4* hp = reinterpret_cast<float4*>(g_Bhi + (size_t)warp * DD);
    float4* lp = reinterpret_cast<float4*>(g_Blo + (size_t)warp * DD);
    hp[lane]      = make_float4(hi[0], hi[1], hi[2], hi[3]);
    hp[lane + 32] = make_float4(hi[4], hi[5], hi[6], hi[7]);
    lp[lane]      = make_float4(lo[0], lo[1], lo[2], lo[3]);
    lp[lane + 32] = make_float4(lo[4], lo[5], lo[6], lo[7]);
}

// ============================================================================
// Transpose z (B,D,HW) -> token-major (N,D) with tf32 hi/lo split.
// ============================================================================
__global__ void transpose_split(const float* __restrict__ z) {
    __shared__ float t[32][33];
    int tx = threadIdx.x, ty = threadIdx.y;
    int hw0 = blockIdx.x * 32, d0 = blockIdx.y * 32, b = blockIdx.z;
    const float* zb = z + (size_t)b * DD * HWSZ;
    #pragma unroll
    for (int i = 0; i < 4; i++) {
        int d = d0 + ty + i * 8;
        t[ty + i * 8][tx] = zb[(size_t)d * HWSZ + hw0 + tx];
    }
    __syncthreads();
    #pragma unroll
    for (int i = 0; i < 4; i++) {
        int hwl = ty + i * 8;
        int n = b * HWSZ + hw0 + hwl;
        float v = t[tx][hwl];
        float h = tf32_rna(v);
        float l = tf32_rna(v - h);
        g_Ahi[(size_t)n * DD + d0 + tx] = h;
        g_Alo[(size_t)n * DD + d0 + tx] = l;
    }
}

// ============================================================================
// 3xTF32 mma.sync GEMM + fused per-slice argmax.
// Grid: 2048 CTAs = (tile 0..255) x (kslice 0..7). 256 threads = 8 warps (2x4).
// Warptile 64x32. D-chunks of 32 double-buffered via cp.async.
// SMEM per stage: {Ah,Al,Bh,Bl} 128 rows x 36-float padded stride (18432B each).
// ============================================================================
#define STRD   36
#define BUF_B  18432            // 128*36*4 bytes
#define STG_B  (4*BUF_B)        // 73728
#define GSMEM  (2*STG_B)        // 147456

__global__ __launch_bounds__(256, 1) void gemm_argmax_mma() {
    extern __shared__ float sm[];
    const uint32_t sbase = smem_to_u32(sm);
    const int tid  = threadIdx.x;
    const int warp = tid >> 5;
    const int lane = tid & 31;
    const int wr = warp >> 2;        // 0..1  (64-row band)
    const int wc = warp & 3;         // 0..3  (32-col band)
    const int g  = lane >> 2;        // 0..7
    const int tg = lane & 3;         // 0..3

    const int tile    = blockIdx.x >> 3;
    const int slice   = blockIdx.x & 7;
    const int rowBase = tile * 128;
    const int kBase   = slice * KSLICE;

    float acc[4][4][4];
    #pragma unroll
    for (int mt = 0; mt < 4; mt++)
        #pragma unroll
        for (int nt = 0; nt < 4; nt++)
            #pragma unroll
            for (int q = 0; q < 4; q++) acc[mt][nt][q] = 0.0f;

    float bestV[8];
    int   bestI[8];
    #pragma unroll
    for (int i = 0; i < 8; i++) { bestV[i] = -INFINITY; bestI[i] = 0; }

    // ---- stage loader (all 256 threads; 16 cp.async each) ----
    auto load_stage = [&](int it) {
        int stage = it & 1;
        int k0 = kBase + (it >> 3) * 128;
        int d0 = (it & 7) * 32;
        uint32_t sb = sbase + stage * STG_B;
        #pragma unroll
        for (int i = 0; i < 4; i++) {
            int lin = tid + i * 256;         // 0..1023
            int r = lin >> 3, c = lin & 7;
            uint32_t off = (uint32_t)(r * 144 + c * 16);
            size_t ao = (size_t)(rowBase + r) * DD + d0 + c * 4;
            size_t bo = (size_t)(k0 + r) * DD + d0 + c * 4;
            cpasync16(sb + off,             g_Ahi + ao);
            cpasync16(sb + BUF_B + off,     g_Alo + ao);
            cpasync16(sb + 2 * BUF_B + off, g_Bhi + bo);
            cpasync16(sb + 3 * BUF_B + off, g_Blo + bo);
        }
        CPASYNC_COMMIT();
    };

    load_stage(0);

    for (int it = 0; it < 64; it++) {
        if (it + 1 < 64) { load_stage(it + 1); CPASYNC_WAIT(1); }
        else             { CPASYNC_WAIT(0); }
        __syncthreads();

        int stage = it & 1;
        const float* Ah = sm + stage * (STG_B / 4);
        const float* Al = Ah + BUF_B / 4;
        const float* Bh = Ah + 2 * (BUF_B / 4);
        const float* Bl = Ah + 3 * (BUF_B / 4);

        #pragma unroll
        for (int ks = 0; ks < 4; ks++) {
            int kb = ks * 8 + tg;
            float ah[4][4], al[4][4], bh[4][2], bl[4][2];
            #pragma unroll
            for (int mt = 0; mt < 4; mt++) {
                int r0 = (wr * 64 + mt * 16 + g) * STRD + kb;
                ah[mt][0] = Ah[r0];           ah[mt][1] = Ah[r0 + 8 * STRD];
                ah[mt][2] = Ah[r0 + 4];       ah[mt][3] = Ah[r0 + 8 * STRD + 4];
                al[mt][0] = Al[r0];           al[mt][1] = Al[r0 + 8 * STRD];
                al[mt][2] = Al[r0 + 4];       al[mt][3] = Al[r0 + 8 * STRD + 4];
            }
            #pragma unroll
            for (int nt = 0; nt < 4; nt++) {
                int c0 = (wc * 32 + nt * 8 + g) * STRD + kb;
                bh[nt][0] = Bh[c0];  bh[nt][1] = Bh[c0 + 4];
                bl[nt][0] = Bl[c0];  bl[nt][1] = Bl[c0 + 4];
            }
            #pragma unroll
            for (int mt = 0; mt < 4; mt++)
                #pragma unroll
                for (int nt = 0; nt < 4; nt++) {
                    mma8(acc[mt][nt], ah[mt], bh[nt]);
                    mma8(acc[mt][nt], ah[mt], bl[nt]);
                    mma8(acc[mt][nt], al[mt], bh[nt]);
                }
        }

        if ((it & 7) == 7) {
            // finished D=256 for this 128-col K-tile: fold into running argmax
            int k0 = kBase + (it >> 3) * 128;
            #pragma unroll
            for (int mt = 0; mt < 4; mt++)
                #pragma unroll
                for (int rr = 0; rr < 2; rr++) {
                    int slot = mt * 2 + rr;
                    #pragma unroll
                    for (int nt = 0; nt < 4; nt++)
                        #pragma unroll
                        for (int j = 0; j < 2; j++) {
                            float v = acc[mt][nt][rr * 2 + j];
                            if (v > bestV[slot]) {
                                bestV[slot] = v;
                                bestI[slot] = k0 + wc * 32 + nt * 8 + tg * 2 + j;
                            }
                        }
                }
            #pragma unroll
            for (int mt = 0; mt < 4; mt++)
                #pragma unroll
                for (int nt = 0; nt < 4; nt++)
                    #pragma unroll
                    for (int q = 0; q < 4; q++) acc[mt][nt][q] = 0.0f;
        }
        __syncthreads();
    }

    // ---- cross-thread per-row reduction (16 contributors per row) ----
    float* sv = sm;                       // 128*16 floats
    int*   si = (int*)(sm + 2048);        // 128*16 ints
    #pragma unroll
    for (int slot = 0; slot < 8; slot++) {
        int m = wr * 64 + (slot >> 1) * 16 + (slot & 1) * 8 + g;
        sv[m * 16 + wc * 4 + tg] = bestV[slot];
        si[m * 16 + wc * 4 + tg] = bestI[slot];
    }
    __syncthreads();
    if (tid < 128) {
        float bv = sv[tid * 16];
        int   bi = si[tid * 16];
        #pragma unroll
        for (int t = 1; t < 16; t++) {
            float v = sv[tid * 16 + t];
            int  id = si[tid * 16 + t];
            if (v > bv || (v == bv && id < bi)) { bv = v; bi = id; }
        }
        g_pv[blockIdx.x * 128 + tid] = bv;
        g_pi[blockIdx.x * 128 + tid] = bi;
    }
}

// ============================================================================
// Merge the 8 K-slice partial bests per token.
// ============================================================================
__global__ void merge_kernel() {
    int tile = blockIdx.x;
    int m = threadIdx.x;
    float bv = -INFINITY; int bi = 0;
    #pragma unroll
    for (int s = 0; s < NSLICE; s++) {
        float v = g_pv[(tile * NSLICE + s) * 128 + m];
        int  id = g_pi[(tile * NSLICE + s) * 128 + m];
        if (v > bv || (v == bv && id < bi)) { bv = v; bi = id; }
    }
    g_idx[tile * 128 + m] = bi;
}

// ============================================================================
// EMA scatter: avg_out[idx[n]][d] += 0.01*z[n][d] ; cs_out[idx[n]] += 0.01
// ============================================================================
__global__ void scatter_kernel(const float* __restrict__ z,
                               float* __restrict__ avg_out,
                               float* __restrict__ cs_out) {
    int t = blockIdx.x * blockDim.x + threadIdx.x;
    if (t >= ZELEMS) return;
    int hw = t & (HWSZ - 1);
    int bd = t >> 12;
    int d  = bd & (DD - 1);
    int b  = bd >> 8;
    int n  = (b << 12) | hw;
    int id = __ldg(&g_idx[n]);
    float v = z[t];
    atomicAdd(&avg_out[id * DD + d], 0.01f * v);
    if (d == 0) atomicAdd(&cs_out[id], 0.01f);
}

// ============================================================================
// Output gather
// ============================================================================
__global__ void output_kernel(const float* __restrict__ z,
                              const float* __restrict__ embedding,
                              float* __restrict__ zst,
                              float* __restrict__ zq,
                              float* __restrict__ idxf) {
    int t = blockIdx.x * blockDim.x + threadIdx.x;
    if (t < NTOK) idxf[t] = (float)g_idx[t];
    if (t >= ZELEMS) return;
    int hw = t & (HWSZ - 1);
    int bd = t >> 12;
    int d  = bd & (DD - 1);
    int b  = bd >> 8;
    int n  = (b << 12) | hw;
    int id = __ldg(&g_idx[n]);
    float e  = __ldg(&embedding[id * DD + d]);
    float zv = z[t];
    zq[t]  = e;
    zst[t] = zv + (e - zv);
}

// ============================================================================
extern "C" void kernel_launch(void* const* d_in, const int* in_sizes, int n_in,
                              void* d_out, int out_size) {
    const float* z            = (const float*)d_in[0];
    const float* embedding    = (const float*)d_in[1];
    const float* cluster_size = (const float*)d_in[2];
    const float* embed_avg    = (const float*)d_in[3];

    float* out   = (float*)d_out;
    float* zst_o = out + OFF_ZST;
    float* idx_o = out + OFF_IDX;
    float* zq_o  = out + OFF_ZQ;
    float* emb_o = out + OFF_EMB;
    float* cs_o  = out + OFF_CS;
    float* avg_o = out + OFF_AVG;

    init_kernel<<<(NK * DD + 255) / 256, 256>>>(cluster_size, embed_avg, cs_o, avg_o);

    norm_split_embed<<<NK / 8, 256>>>(embedding);
    transpose_split<<<dim3(HWSZ / 32, DD / 32, 8), dim3(32, 8)>>>(z);

    static bool attr_set = false;
    if (!attr_set) {
        cudaFuncSetAttribute(gemm_argmax_mma,
                             cudaFuncAttributeMaxDynamicSharedMemorySize, GSMEM);
        attr_set = true;
    }
    gemm_argmax_mma<<<NTILE * NSLICE, 256, GSMEM>>>();

    merge_kernel<<<NTILE, 128>>>();

    scatter_kernel<<<ZELEMS / 256, 256>>>(z, avg_o, cs_o);

    output_kernel<<<ZELEMS / 256, 256>>>(z, embedding, zst_o, zq_o, idx_o);

    norm_rows_kernel<<<NK / 8, 256>>>(avg_o, emb_o, NK);
}

// round 4
// speedup vs baseline: 1.8584x; 1.0003x over previous
#include <cuda_runtime.h>
#include <cuda_bf16.h>
#include <math.h>
#include <stdint.h>

// Problem constants
#define NK    8192        // num_embeddings
#define DD    256         // embedding_dim
#define NTOK  32768       // B*H*W
#define HWSZ  4096        // H*W
#define ZELEMS 8388608    // B*D*H*W

// Output layout offsets (float32, reference return order)
#define OFF_ZST  0
#define OFF_IDX  8388608
#define OFF_ZQ   8421376
#define OFF_EMB  16809984
#define OFF_CS   18907136
#define OFF_AVG  18915328

// Coarse tiling: CTA = 64 tokens x 1024 codes (one k-slice of 8)
#define NSLICE 8
#define KSLICE 1024
#define NTILE2 512        // NTOK / 64

// Scratch (__device__ globals: allocation-free)
// hi arrays are stored with a per-8-column permutation p(c)=(c&3)*2+(c>>2)
// so mma fragment pairs (tg, tg+4) are adjacent -> LDS.64 loads.
// lo arrays hold the EXACT fp32 residual (a - tf32(a)): hi+lo reconstructs
// the value exactly for the rescore path.
__device__ float g_Ahi[NTOK * DD];
__device__ float g_Alo[NTOK * DD];
__device__ float g_Bhi[NK * DD];
__device__ float g_Blo[NK * DD];
__device__ float g_nAh2[NTOK];            // per-token ||ah||^2
__device__ float g_nAl2[NTOK];            // per-token ||al||^2
__device__ int   g_maxBlBits;             // max_j ||bl_j|| as float bits
__device__ float2 g_p2v[NTILE2 * NSLICE * 64];   // coarse top-2 values
__device__ int2   g_p2i[NTILE2 * NSLICE * 64];   // coarse top-2 indices
__device__ int   g_flagCnt;
__device__ int   g_flagTok[NTOK];
__device__ float g_rv[NTOK * 8];          // rescore partial best per slice
__device__ int   g_ri[NTOK * 8];
__device__ int   g_idx[NTOK];

// ============================================================================
// helpers
// ============================================================================
__device__ __forceinline__ uint32_t smem_to_u32(const void* p) {
    uint32_t a;
    asm("{ .reg .u64 t; cvta.to.shared.u64 t, %1; cvt.u32.u64 %0, t; }" : "=r"(a) : "l"(p));
    return a;
}
__device__ __forceinline__ void cpasync16(uint32_t dst, const void* src) {
    asm volatile("cp.async.cg.shared.global [%0], [%1], 16;" :: "r"(dst), "l"(src));
}
#define CPASYNC_COMMIT() asm volatile("cp.async.commit_group;" ::: "memory")
#define CPASYNC_WAIT(n)  asm volatile("cp.async.wait_group %0;" :: "n"(n) : "memory")

__device__ __forceinline__ float tf32_rna(float x) {
    uint32_t u;
    asm("cvt.rna.tf32.f32 %0, %1;" : "=r"(u) : "f"(x));
    return __uint_as_float(u);
}

// m16n8k8 tf32 mma
__device__ __forceinline__ void mma8(float* c, const float* a, const float* b) {
    asm volatile(
        "mma.sync.aligned.m16n8k8.row.col.f32.tf32.tf32.f32 "
        "{%0,%1,%2,%3}, {%4,%5,%6,%7}, {%8,%9}, {%0,%1,%2,%3};"
        : "+f"(c[0]), "+f"(c[1]), "+f"(c[2]), "+f"(c[3])
        : "r"(__float_as_uint(a[0])), "r"(__float_as_uint(a[1])),
          "r"(__float_as_uint(a[2])), "r"(__float_as_uint(a[3])),
          "r"(__float_as_uint(b[0])), "r"(__float_as_uint(b[1])));
}

// permuted column position within a row of 256: groups of 8, p=(c&3)*2+(c>>2)
__device__ __forceinline__ int dperm(int c) {
    int inner = c & 7;
    return (c & ~7) + ((inner & 3) * 2) + (inner >> 2);
}

#define TOP2_UPD(v, i, V1, I1, V2, I2) do {                          \
    float _v = (v); int _i = (i);                                    \
    if (_v > (V1) || (_v == (V1) && _i < (I1))) {                    \
        (V2) = (V1); (I2) = (I1); (V1) = _v; (I1) = _i;              \
    } else if (_v > (V2) || (_v == (V2) && _i < (I2))) {             \
        (V2) = _v; (I2) = _i;                                        \
    }                                                                \
} while (0)

// ============================================================================
// init: EMA decay init + reset all per-launch scratch accumulators
// ============================================================================
__global__ void init_kernel(const float* __restrict__ cluster_size,
                            const float* __restrict__ embed_avg,
                            float* __restrict__ cs_out,
                            float* __restrict__ avg_out) {
    int t = blockIdx.x * blockDim.x + threadIdx.x;
    if (t < NK) cs_out[t] = 0.99f * cluster_size[t];
    if (t < NK * DD) avg_out[t] = 0.99f * embed_avg[t];
    if (t < NTOK) { g_nAh2[t] = 0.0f; g_nAl2[t] = 0.0f; }
    if (t == 0) { g_maxBlBits = 0; g_flagCnt = 0; }
}

// ============================================================================
// Row L2-normalize (final new_embedding). One warp per row.
// ============================================================================
__global__ void norm_rows_kernel(const float* __restrict__ in,
                                 float* __restrict__ out, int nrows) {
    int warp = (blockIdx.x * blockDim.x + threadIdx.x) >> 5;
    int lane = threadIdx.x & 31;
    if (warp >= nrows) return;
    const float4* ip = reinterpret_cast<const float4*>(in + (size_t)warp * DD);
    float4 v0 = ip[lane];
    float4 v1 = ip[lane + 32];
    float s = v0.x*v0.x + v0.y*v0.y + v0.z*v0.z + v0.w*v0.w
            + v1.x*v1.x + v1.y*v1.y + v1.z*v1.z + v1.w*v1.w;
    #pragma unroll
    for (int off = 16; off > 0; off >>= 1) s += __shfl_xor_sync(0xFFFFFFFFu, s, off);
    float nrm = fmaxf(sqrtf(s), 1e-12f);
    float4 o0, o1;
    o0.x = v0.x/nrm; o0.y = v0.y/nrm; o0.z = v0.z/nrm; o0.w = v0.w/nrm;
    o1.x = v1.x/nrm; o1.y = v1.y/nrm; o1.z = v1.z/nrm; o1.w = v1.w/nrm;
    float4* op = reinterpret_cast<float4*>(out + (size_t)warp * DD);
    op[lane] = o0; op[lane + 32] = o1;
}

// ============================================================================
// normalize codebook rows + exact tf32 split (permuted) + ||bl|| max.
// One warp per row.
// ============================================================================
__global__ void norm_split_embed(const float* __restrict__ in) {
    int warp = (blockIdx.x * blockDim.x + threadIdx.x) >> 5;
    int lane = threadIdx.x & 31;
    if (warp >= NK) return;
    const float4* ip = reinterpret_cast<const float4*>(in + (size_t)warp * DD);
    float4 v0 = ip[lane];
    float4 v1 = ip[lane + 32];
    float s = v0.x*v0.x + v0.y*v0.y + v0.z*v0.z + v0.w*v0.w
            + v1.x*v1.x + v1.y*v1.y + v1.z*v1.z + v1.w*v1.w;
    #pragma unroll
    for (int off = 16; off > 0; off >>= 1) s += __shfl_xor_sync(0xFFFFFFFFu, s, off);
    float inv = 1.0f / fmaxf(sqrtf(s), 1e-12f);
    float vv[8] = {v0.x, v0.y, v0.z, v0.w, v1.x, v1.y, v1.z, v1.w};
    float bl2 = 0.0f;
    #pragma unroll
    for (int i = 0; i < 8; i++) {
        int c = (i < 4) ? (lane * 4 + i) : (128 + lane * 4 + (i - 4));
        float v = vv[i] * inv;
        float h = tf32_rna(v);
        float l = v - h;                         // exact residual
        int dp = dperm(c);
        g_Bhi[(size_t)warp * DD + dp] = h;
        g_Blo[(size_t)warp * DD + dp] = l;
        bl2 += l * l;
    }
    #pragma unroll
    for (int off = 16; off > 0; off >>= 1) bl2 += __shfl_xor_sync(0xFFFFFFFFu, bl2, off);
    if (lane == 0) atomicMax(&g_maxBlBits, __float_as_int(sqrtf(bl2)));
}

// ============================================================================
// Transpose z (B,D,HW) -> token-major (N,D), exact tf32 split (permuted),
// and per-token ||ah||^2 / ||al||^2 accumulation.
// ============================================================================
__global__ void transpose_split(const float* __restrict__ z) {
    __shared__ float t[32][33];
    int tx = threadIdx.x, ty = threadIdx.y;
    int hw0 = blockIdx.x * 32, d0 = blockIdx.y * 32, b = blockIdx.z;
    const float* zb = z + (size_t)b * DD * HWSZ;
    #pragma unroll
    for (int i = 0; i < 4; i++) {
        int d = d0 + ty + i * 8;
        t[ty + i * 8][tx] = zb[(size_t)d * HWSZ + hw0 + tx];
    }
    __syncthreads();
    int dp = d0 + dperm(tx);
    #pragma unroll
    for (int i = 0; i < 4; i++) {
        int hwl = ty + i * 8;
        int n = b * HWSZ + hw0 + hwl;
        float v = t[tx][hwl];
        float h = tf32_rna(v);
        float l = v - h;                         // exact residual
        g_Ahi[(size_t)n * DD + dp] = h;
        g_Alo[(size_t)n * DD + dp] = l;
        float hh = h * h, ll = l * l;
        #pragma unroll
        for (int off = 16; off > 0; off >>= 1) {
            hh += __shfl_xor_sync(0xFFFFFFFFu, hh, off);
            ll += __shfl_xor_sync(0xFFFFFFFFu, ll, off);
        }
        if (tx == 0) {
            atomicAdd(&g_nAh2[n], hh);
            atomicAdd(&g_nAl2[n], ll);
        }
    }
}

// ============================================================================
// Coarse GEMM (1-pass tf32 hi*hi) + top-2 argmax per (tile, slice).
// Grid 4096 = 512 token-tiles x 8 k-slices. 256 threads, 8 warps (2x4),
// warptile 32x32. 2 CTAs/SM. Stage = {Ah 64x32, Bh 128x32}, stride 40 floats.
// ============================================================================
#define CW    40
#define ABUF  10240          // 64*40*4
#define BBUF  20480          // 128*40*4
#define STG   (ABUF + BBUF)  // 30720
#define GSM   (2 * STG)      // 61440

__global__ __launch_bounds__(256, 2) void coarse_gemm() {
    extern __shared__ float sm[];
    const uint32_t sbase = smem_to_u32(sm);
    const int tid  = threadIdx.x;
    const int warp = tid >> 5;
    const int lane = tid & 31;
    const int wr = warp >> 2;        // 0..1
    const int wc = warp & 3;         // 0..3
    const int g  = lane >> 2;        // 0..7
    const int tg = lane & 3;         // 0..3

    const int tile    = blockIdx.x >> 3;
    const int slice   = blockIdx.x & 7;
    const int rowBase = tile * 64;
    const int kBase   = slice * KSLICE;

    float acc[2][4][4];
    #pragma unroll
    for (int mt = 0; mt < 2; mt++)
        #pragma unroll
        for (int nt = 0; nt < 4; nt++)
            #pragma unroll
            for (int q = 0; q < 4; q++) acc[mt][nt][q] = 0.0f;

    float v1[4], v2[4];
    int   i1[4], i2[4];
    #pragma unroll
    for (int s = 0; s < 4; s++) {
        v1[s] = -INFINITY; v2[s] = -INFINITY;
        i1[s] = 0x7fffffff; i2[s] = 0x7fffffff;
    }

    auto load_stage = [&](int it) {
        int stage = it & 1;
        int k0 = kBase + (it >> 3) * 128;
        int d0 = (it & 7) * 32;
        uint32_t sb = sbase + stage * STG;
        #pragma unroll
        for (int i = 0; i < 6; i++) {
            int ch = tid + i * 256;
            uint32_t dst; const float* src;
            if (ch < 512) {
                int r = ch >> 3, c = ch & 7;
                dst = sb + (uint32_t)(r * 160 + c * 16);
                src = g_Ahi + ((size_t)(rowBase + r) * DD + d0 + c * 4);
            } else {
                int c2 = ch - 512;
                int r = c2 >> 3, c = c2 & 7;
                dst = sb + ABUF + (uint32_t)(r * 160 + c * 16);
                src = g_Bhi + ((size_t)(k0 + r) * DD + d0 + c * 4);
            }
            cpasync16(dst, src);
        }
        CPASYNC_COMMIT();
    };

    load_stage(0);

    for (int it = 0; it < 64; it++) {
        if (it + 1 < 64) { load_stage(it + 1); CPASYNC_WAIT(1); }
        else             { CPASYNC_WAIT(0); }
        __syncthreads();

        int stage = it & 1;
        const float* Ah = sm + stage * (STG / 4);
        const float* Bh = Ah + (ABUF / 4);

        #pragma unroll
        for (int ks = 0; ks < 4; ks++) {
            int kp = ks * 8 + 2 * tg;
            float2 af[2][2], bf[4];
            #pragma unroll
            for (int mt = 0; mt < 2; mt++) {
                const float* p = Ah + (wr * 32 + mt * 16 + g) * CW + kp;
                af[mt][0] = *(const float2*)p;
                af[mt][1] = *(const float2*)(p + 8 * CW);
            }
            #pragma unroll
            for (int nt = 0; nt < 4; nt++)
                bf[nt] = *(const float2*)(Bh + (wc * 32 + nt * 8 + g) * CW + kp);
            #pragma unroll
            for (int mt = 0; mt < 2; mt++)
                #pragma unroll
                for (int nt = 0; nt < 4; nt++) {
                    float a[4] = {af[mt][0].x, af[mt][1].x, af[mt][0].y, af[mt][1].y};
                    float b[2] = {bf[nt].x, bf[nt].y};
                    mma8(acc[mt][nt], a, b);
                }
        }

        if ((it & 7) == 7) {
            int k0 = kBase + (it >> 3) * 128;
            #pragma unroll
            for (int mt = 0; mt < 2; mt++)
                #pragma unroll
                for (int half = 0; half < 2; half++) {
                    int slot = mt * 2 + half;
                    #pragma unroll
                    for (int nt = 0; nt < 4; nt++)
                        #pragma unroll
                        for (int j = 0; j < 2; j++) {
                            float v = acc[mt][nt][half * 2 + j];
                            int ci = k0 + wc * 32 + nt * 8 + tg * 2 + j;
                            TOP2_UPD(v, ci, v1[slot], i1[slot], v2[slot], i2[slot]);
                        }
                }
            #pragma unroll
            for (int mt = 0; mt < 2; mt++)
                #pragma unroll
                for (int nt = 0; nt < 4; nt++)
                    #pragma unroll
                    for (int q = 0; q < 4; q++) acc[mt][nt][q] = 0.0f;
        }
        __syncthreads();
    }

    // cross-thread top-2 merge: 16 contributors (wc x tg) per row
    float2* sv = (float2*)sm;
    int2*   si = (int2*)(sm + 2048);
    #pragma unroll
    for (int slot = 0; slot < 4; slot++) {
        int row = wr * 32 + (slot >> 1) * 16 + (slot & 1) * 8 + g;
        int ent = row * 16 + wc * 4 + tg;
        sv[ent] = make_float2(v1[slot], v2[slot]);
        si[ent] = make_int2(i1[slot], i2[slot]);
    }
    __syncthreads();
    if (tid < 64) {
        float V1 = -INFINITY, V2 = -INFINITY;
        int I1 = 0x7fffffff, I2 = 0x7fffffff;
        #pragma unroll
        for (int t = 0; t < 16; t++) {
            float2 v = sv[tid * 16 + t];
            int2  ii = si[tid * 16 + t];
            TOP2_UPD(v.x, ii.x, V1, I1, V2, I2);
            TOP2_UPD(v.y, ii.y, V1, I1, V2, I2);
        }
        size_t e = (size_t)blockIdx.x * 64 + tid;
        g_p2v[e] = make_float2(V1, V2);
        g_p2i[e] = make_int2(I1, I2);
    }
}

// ============================================================================
// Merge slices + rigorous margin test. Flags uncertain tokens for rescore.
// ============================================================================
__global__ void merge_kernel() {
    int n = blockIdx.x * blockDim.x + threadIdx.x;
    if (n >= NTOK) return;
    int tile = n >> 6, row = n & 63;
    float V1 = -INFINITY, V2 = -INFINITY;
    int I1 = 0x7fffffff, I2 = 0x7fffffff;
    #pragma unroll
    for (int s = 0; s < NSLICE; s++) {
        size_t e = ((size_t)(tile * NSLICE + s)) * 64 + row;
        float2 v = g_p2v[e];
        int2  ii = g_p2i[e];
        TOP2_UPD(v.x, ii.x, V1, I1, V2, I2);
        TOP2_UPD(v.y, ii.y, V1, I1, V2, I2);
    }
    float maxBl = __int_as_float(g_maxBlBits);
    // |exact - coarse| <= ||al||*||b|| + ||ah||*maxBl + accumulation slack
    float nAh = sqrtf(g_nAh2[n]);
    float nAl = sqrtf(g_nAl2[n]);
    float margin = nAl * 1.0001f + nAh * (maxBl + 5e-5f);
    if (V1 - V2 >= 2.0f * margin) {
        g_idx[n] = I1;
    } else {
        int s = atomicAdd(&g_flagCnt, 1);
        g_flagTok[s] = n;
        g_idx[n] = I1;   // placeholder; overwritten by merge2
    }
}

// ============================================================================
// Exact fp32 rescore over ALL codes for flagged tokens (a=ah+al, b=bh+bl
// reconstruct exactly). Grid covers worst case; CTAs past count exit.
// ============================================================================
__global__ __launch_bounds__(256) void rescore_kernel() {
    __shared__ float As[16][128];
    __shared__ float Bs[16][132];
    __shared__ int toks[128];
    int count = g_flagCnt;
    int tile = blockIdx.x >> 3, slice = blockIdx.x & 7;
    int base = tile * 128;
    if (base >= count) return;
    int tid = threadIdx.x;
    if (tid < 128) toks[tid] = (base + tid < count) ? g_flagTok[base + tid] : g_flagTok[0];
    __syncthreads();
    int tx = tid & 15, ty = tid >> 4;
    int kBase = slice * KSLICE;

    float bestV[8];
    int   bestI[8];
    #pragma unroll
    for (int i = 0; i < 8; i++) { bestV[i] = -INFINITY; bestI[i] = 0; }

    for (int k0 = 0; k0 < KSLICE; k0 += 128) {
        float acc[8][8];
        #pragma unroll
        for (int i = 0; i < 8; i++)
            #pragma unroll
            for (int j = 0; j < 8; j++) acc[i][j] = 0.0f;

        for (int d0 = 0; d0 < DD; d0 += 16) {
            __syncthreads();
            #pragma unroll
            for (int i = 0; i < 8; i++) {
                int lin = tid + i * 256;
                int dk = lin >> 7, m = lin & 127;
                size_t o = (size_t)toks[m] * DD + d0 + dk;
                As[dk][m] = g_Ahi[o] + g_Alo[o];
            }
            #pragma unroll
            for (int i = 0; i < 8; i++) {
                int lin = tid + i * 256;
                int kn = lin >> 4, dk = lin & 15;
                size_t o = (size_t)(kBase + k0 + kn) * DD + d0 + dk;
                Bs[dk][kn] = g_Bhi[o] + g_Blo[o];
            }
            __syncthreads();
            #pragma unroll
            for (int dk = 0; dk < 16; dk++) {
                float a[8], bb[8];
                #pragma unroll
                for (int i = 0; i < 8; i++) a[i] = As[dk][ty * 8 + i];
                #pragma unroll
                for (int j = 0; j < 8; j++) bb[j] = Bs[dk][tx * 8 + j];
                #pragma unroll
                for (int i = 0; i < 8; i++)
                    #pragma unroll
                    for (int j = 0; j < 8; j++)
                        acc[i][j] = fmaf(a[i], bb[j], acc[i][j]);
            }
        }
        #pragma unroll
        for (int i = 0; i < 8; i++)
            #pragma unroll
            for (int j = 0; j < 8; j++) {
                float v = acc[i][j];
                if (v > bestV[i]) { bestV[i] = v; bestI[i] = kBase + k0 + tx * 8 + j; }
            }
    }

    __syncthreads();
    float* sv = &As[0][0];
    int*   si = (int*)&Bs[0][0];
    #pragma unroll
    for (int i = 0; i < 8; i++) {
        int m = ty * 8 + i;
        sv[m * 16 + tx] = bestV[i];
        si[m * 16 + tx] = bestI[i];
    }
    __syncthreads();
    if (tid < 128 && base + tid < count) {
        float bv = sv[tid * 16];
        int   bi = si[tid * 16];
        #pragma unroll
        for (int t = 1; t < 16; t++) {
            float v = sv[tid * 16 + t];
            int  id = si[tid * 16 + t];
            if (v > bv || (v == bv && id < bi)) { bv = v; bi = id; }
        }
        g_rv[(size_t)(base + tid) * 8 + slice] = bv;
        g_ri[(size_t)(base + tid) * 8 + slice] = bi;
    }
}

// ============================================================================
// merge2: fold 8 slice partials for flagged tokens -> final idx
// ============================================================================
__global__ void merge2_kernel() {
    int slot = blockIdx.x * blockDim.x + threadIdx.x;
    if (slot >= g_flagCnt || slot >= NTOK) return;
    float bv = -INFINITY; int bi = 0x7fffffff;
    #pragma unroll
    for (int s = 0; s < 8; s++) {
        float v = g_rv[(size_t)slot * 8 + s];
        int   i = g_ri[(size_t)slot * 8 + s];
        if (v > bv || (v == bv && i < bi)) { bv = v; bi = i; }
    }
    g_idx[g_flagTok[slot]] = bi;
}

// ============================================================================
// EMA scatter: avg_out[idx[n]][d] += 0.01*z[n][d] ; cs_out[idx[n]] += 0.01
// ============================================================================
__global__ void scatter_kernel(const float* __restrict__ z,
                               float* __restrict__ avg_out,
                               float* __restrict__ cs_out) {
    int t = blockIdx.x * blockDim.x + threadIdx.x;
    if (t >= ZELEMS) return;
    int hw = t & (HWSZ - 1);
    int bd = t >> 12;
    int d  = bd & (DD - 1);
    int b  = bd >> 8;
    int n  = (b << 12) | hw;
    int id = __ldg(&g_idx[n]);
    float v = z[t];
    atomicAdd(&avg_out[id * DD + d], 0.01f * v);
    if (d == 0) atomicAdd(&cs_out[id], 0.01f);
}

// ============================================================================
// Output gather
// ============================================================================
__global__ void output_kernel(const float* __restrict__ z,
                              const float* __restrict__ embedding,
                              float* __restrict__ zst,
                              float* __restrict__ zq,
                              float* __restrict__ idxf) {
    int t = blockIdx.x * blockDim.x + threadIdx.x;
    if (t < NTOK) idxf[t] = (float)g_idx[t];
    if (t >= ZELEMS) return;
    int hw = t & (HWSZ - 1);
    int bd = t >> 12;
    int d  = bd & (DD - 1);
    int b  = bd >> 8;
    int n  = (b << 12) | hw;
    int id = __ldg(&g_idx[n]);
    float e  = __ldg(&embedding[id * DD + d]);
    float zv = z[t];
    zq[t]  = e;
    zst[t] = zv + (e - zv);
}

// ============================================================================
extern "C" void kernel_launch(void* const* d_in, const int* in_sizes, int n_in,
                              void* d_out, int out_size) {
    const float* z            = (const float*)d_in[0];
    const float* embedding    = (const float*)d_in[1];
    const float* cluster_size = (const float*)d_in[2];
    const float* embed_avg    = (const float*)d_in[3];

    float* out   = (float*)d_out;
    float* zst_o = out + OFF_ZST;
    float* idx_o = out + OFF_IDX;
    float* zq_o  = out + OFF_ZQ;
    float* emb_o = out + OFF_EMB;
    float* cs_o  = out + OFF_CS;
    float* avg_o = out + OFF_AVG;

    init_kernel<<<(NK * DD + 255) / 256, 256>>>(cluster_size, embed_avg, cs_o, avg_o);

    norm_split_embed<<<NK / 8, 256>>>(embedding);
    transpose_split<<<dim3(HWSZ / 32, DD / 32, 8), dim3(32, 8)>>>(z);

    static bool attr_set = false;
    if (!attr_set) {
        cudaFuncSetAttribute(coarse_gemm,
                             cudaFuncAttributeMaxDynamicSharedMemorySize, GSM);
        attr_set = true;
    }
    coarse_gemm<<<NTILE2 * NSLICE, 256, GSM>>>();

    merge_kernel<<<NTOK / 256, 256>>>();

    rescore_kernel<<<(NTOK / 128) * 8, 256>>>();

    merge2_kernel<<<NTOK / 256, 256>>>();

    scatter_kernel<<<ZELEMS / 256, 256>>>(z, avg_o, cs_o);

    output_kernel<<<ZELEMS / 256, 256>>>(z, embedding, zst_o, zq_o, idx_o);

    norm_rows_kernel<<<NK / 8, 256>>>(avg_o, emb_o, NK);
}

// round 5
// speedup vs baseline: 2.2745x; 1.2239x over previous
#include <cuda_runtime.h>
#include <cuda_bf16.h>
#include <math.h>
#include <stdint.h>

// Problem constants
#define NK    8192
#define DD    256
#define NTOK  32768
#define HWSZ  4096
#define ZELEMS 8388608

// Output layout offsets (float32, reference return order)
#define OFF_ZST  0
#define OFF_IDX  8388608
#define OFF_ZQ   8421376
#define OFF_EMB  16809984
#define OFF_CS   18907136
#define OFF_AVG  18915328

#define NSLICE 8
#define KSLICE 1024
#define NTILE  256        // NTOK / 128

// Scratch (__device__ globals)
__device__ float g_Ahi[NTOK * DD];
__device__ float g_Alo[NTOK * DD];
__device__ float g_Bhi[NK * DD];
__device__ float g_Blo[NK * DD];
__device__ float g_nAh2[NTOK];
__device__ float g_nAl2[NTOK];
__device__ int   g_maxBlBits;
__device__ float2 g_pv[NTILE * NSLICE * 128];   // (V1, V2)
__device__ int    g_pi[NTILE * NSLICE * 128];   // I1
__device__ int   g_flagCnt;
__device__ int   g_flagTok[NTOK];
__device__ float g_rv[NTOK * 8];
__device__ int   g_ri[NTOK * 8];
__device__ int   g_idx[NTOK];

// ============================================================================
// helpers
// ============================================================================
__device__ __forceinline__ uint32_t smem_to_u32(const void* p) {
    uint32_t a;
    asm("{ .reg .u64 t; cvta.to.shared.u64 t, %1; cvt.u32.u64 %0, t; }" : "=r"(a) : "l"(p));
    return a;
}
__device__ __forceinline__ void cpasync16(uint32_t dst, const void* src) {
    asm volatile("cp.async.cg.shared.global [%0], [%1], 16;" :: "r"(dst), "l"(src));
}
#define CPASYNC_COMMIT() asm volatile("cp.async.commit_group;" ::: "memory")
#define CPASYNC_WAIT(n)  asm volatile("cp.async.wait_group %0;" :: "n"(n) : "memory")

__device__ __forceinline__ float tf32_rna(float x) {
    uint32_t u;
    asm("cvt.rna.tf32.f32 %0, %1;" : "=r"(u) : "f"(x));
    return __uint_as_float(u);
}

__device__ __forceinline__ void mma8(float* c, const float* a, const float* b) {
    asm volatile(
        "mma.sync.aligned.m16n8k8.row.col.f32.tf32.tf32.f32 "
        "{%0,%1,%2,%3}, {%4,%5,%6,%7}, {%8,%9}, {%0,%1,%2,%3};"
        : "+f"(c[0]), "+f"(c[1]), "+f"(c[2]), "+f"(c[3])
        : "r"(__float_as_uint(a[0])), "r"(__float_as_uint(a[1])),
          "r"(__float_as_uint(a[2])), "r"(__float_as_uint(a[3])),
          "r"(__float_as_uint(b[0])), "r"(__float_as_uint(b[1])));
}

// permuted column position within 8-groups: p=(c&3)*2+(c>>2)
__device__ __forceinline__ int dperm(int c) {
    int inner = c & 7;
    return (c & ~7) + ((inner & 3) * 2) + (inner >> 2);
}

// ============================================================================
// init
// ============================================================================
__global__ void init_kernel(const float* __restrict__ cluster_size,
                            const float* __restrict__ embed_avg,
                            float* __restrict__ cs_out,
                            float* __restrict__ avg_out) {
    int t = blockIdx.x * blockDim.x + threadIdx.x;
    if (t < NK) cs_out[t] = 0.99f * cluster_size[t];
    if (t < NK * DD) avg_out[t] = 0.99f * embed_avg[t];
    if (t < NTOK) { g_nAh2[t] = 0.0f; g_nAl2[t] = 0.0f; }
    if (t == 0) { g_maxBlBits = 0; g_flagCnt = 0; }
}

// ============================================================================
// Row L2-normalize (final new_embedding). One warp per row.
// ============================================================================
__global__ void norm_rows_kernel(const float* __restrict__ in,
                                 float* __restrict__ out, int nrows) {
    int warp = (blockIdx.x * blockDim.x + threadIdx.x) >> 5;
    int lane = threadIdx.x & 31;
    if (warp >= nrows) return;
    const float4* ip = reinterpret_cast<const float4*>(in + (size_t)warp * DD);
    float4 v0 = ip[lane];
    float4 v1 = ip[lane + 32];
    float s = v0.x*v0.x + v0.y*v0.y + v0.z*v0.z + v0.w*v0.w
            + v1.x*v1.x + v1.y*v1.y + v1.z*v1.z + v1.w*v1.w;
    #pragma unroll
    for (int off = 16; off > 0; off >>= 1) s += __shfl_xor_sync(0xFFFFFFFFu, s, off);
    float nrm = fmaxf(sqrtf(s), 1e-12f);
    float4 o0, o1;
    o0.x = v0.x/nrm; o0.y = v0.y/nrm; o0.z = v0.z/nrm; o0.w = v0.w/nrm;
    o1.x = v1.x/nrm; o1.y = v1.y/nrm; o1.z = v1.z/nrm; o1.w = v1.w/nrm;
    float4* op = reinterpret_cast<float4*>(out + (size_t)warp * DD);
    op[lane] = o0; op[lane + 32] = o1;
}

// ============================================================================
// normalize codebook rows + exact tf32 split (permuted) + max ||bl||.
// ============================================================================
__global__ void norm_split_embed(const float* __restrict__ in) {
    int warp = (blockIdx.x * blockDim.x + threadIdx.x) >> 5;
    int lane = threadIdx.x & 31;
    if (warp >= NK) return;
    const float4* ip = reinterpret_cast<const float4*>(in + (size_t)warp * DD);
    float4 v0 = ip[lane];
    float4 v1 = ip[lane + 32];
    float s = v0.x*v0.x + v0.y*v0.y + v0.z*v0.z + v0.w*v0.w
            + v1.x*v1.x + v1.y*v1.y + v1.z*v1.z + v1.w*v1.w;
    #pragma unroll
    for (int off = 16; off > 0; off >>= 1) s += __shfl_xor_sync(0xFFFFFFFFu, s, off);
    float inv = 1.0f / fmaxf(sqrtf(s), 1e-12f);
    float vv[8] = {v0.x, v0.y, v0.z, v0.w, v1.x, v1.y, v1.z, v1.w};
    float bl2 = 0.0f;
    #pragma unroll
    for (int i = 0; i < 8; i++) {
        int c = (i < 4) ? (lane * 4 + i) : (128 + lane * 4 + (i - 4));
        float v = vv[i] * inv;
        float h = tf32_rna(v);
        float l = v - h;
        int dp = dperm(c);
        g_Bhi[(size_t)warp * DD + dp] = h;
        g_Blo[(size_t)warp * DD + dp] = l;
        bl2 += l * l;
    }
    #pragma unroll
    for (int off = 16; off > 0; off >>= 1) bl2 += __shfl_xor_sync(0xFFFFFFFFu, bl2, off);
    if (lane == 0) atomicMax(&g_maxBlBits, __float_as_int(sqrtf(bl2)));
}

// ============================================================================
// Transpose z -> token-major, exact tf32 split (permuted), norm accumulation.
// ============================================================================
__global__ void transpose_split(const float* __restrict__ z) {
    __shared__ float t[32][33];
    int tx = threadIdx.x, ty = threadIdx.y;
    int hw0 = blockIdx.x * 32, d0 = blockIdx.y * 32, b = blockIdx.z;
    const float* zb = z + (size_t)b * DD * HWSZ;
    #pragma unroll
    for (int i = 0; i < 4; i++) {
        int d = d0 + ty + i * 8;
        t[ty + i * 8][tx] = zb[(size_t)d * HWSZ + hw0 + tx];
    }
    __syncthreads();
    int dp = d0 + dperm(tx);
    #pragma unroll
    for (int i = 0; i < 4; i++) {
        int hwl = ty + i * 8;
        int n = b * HWSZ + hw0 + hwl;
        float v = t[tx][hwl];
        float h = tf32_rna(v);
        float l = v - h;
        g_Ahi[(size_t)n * DD + dp] = h;
        g_Alo[(size_t)n * DD + dp] = l;
        float hh = h * h, ll = l * l;
        #pragma unroll
        for (int off = 16; off > 0; off >>= 1) {
            hh += __shfl_xor_sync(0xFFFFFFFFu, hh, off);
            ll += __shfl_xor_sync(0xFFFFFFFFu, ll, off);
        }
        if (tx == 0) {
            atomicAdd(&g_nAh2[n], hh);
            atomicAdd(&g_nAl2[n], ll);
        }
    }
}

// ============================================================================
// Coarse GEMM: CTA = 128 tokens x 1024 codes (k-slice). 8 warps (2x4),
// warptile 64x32. 2 CTAs/SM. Cheap tree-max epilogue with safe second-best.
// ============================================================================
#define CW    40
#define ABUF  20480            // 128*40*4
#define STG   (2*ABUF)         // 40960 : Ah + Bh
#define GSM   (2*STG)          // 81920 : double buffer

__global__ __launch_bounds__(256, 2) void coarse_gemm() {
    extern __shared__ float sm[];
    const uint32_t sbase = smem_to_u32(sm);
    const int tid  = threadIdx.x;
    const int warp = tid >> 5;
    const int lane = tid & 31;
    const int wr = warp >> 2;        // 0..1  (64-row band)
    const int wc = warp & 3;         // 0..3  (32-col band)
    const int g  = lane >> 2;        // 0..7
    const int tg = lane & 3;         // 0..3

    const int tile    = blockIdx.x >> 3;
    const int slice   = blockIdx.x & 7;
    const int rowBase = tile * 128;
    const int kBase   = slice * KSLICE;

    float acc[4][4][4];
    #pragma unroll
    for (int mt = 0; mt < 4; mt++)
        #pragma unroll
        for (int nt = 0; nt < 4; nt++)
            #pragma unroll
            for (int q = 0; q < 4; q++) acc[mt][nt][q] = 0.0f;

    float bestV[8], secV[8];
    int   bestI[8];
    #pragma unroll
    for (int s = 0; s < 8; s++) {
        bestV[s] = -INFINITY; secV[s] = -INFINITY; bestI[s] = 0x7fffffff;
    }

    auto load_stage = [&](int it) {
        int stage = it & 1;
        int k0 = kBase + (it >> 3) * 128;
        int d0 = (it & 7) * 32;
        uint32_t sb = sbase + stage * STG;
        #pragma unroll
        for (int i = 0; i < 8; i++) {
            int ch = tid + i * 256;          // 0..2047
            uint32_t dst; const float* src;
            if (ch < 1024) {
                int r = ch >> 3, c = ch & 7;
                dst = sb + (uint32_t)(r * 160 + c * 16);
                src = g_Ahi + ((size_t)(rowBase + r) * DD + d0 + c * 4);
            } else {
                int c2 = ch - 1024;
                int r = c2 >> 3, c = c2 & 7;
                dst = sb + ABUF + (uint32_t)(r * 160 + c * 16);
                src = g_Bhi + ((size_t)(k0 + r) * DD + d0 + c * 4);
            }
            cpasync16(dst, src);
        }
        CPASYNC_COMMIT();
    };

    load_stage(0);

    for (int it = 0; it < 64; it++) {
        if (it + 1 < 64) { load_stage(it + 1); CPASYNC_WAIT(1); }
        else             { CPASYNC_WAIT(0); }
        __syncthreads();

        int stage = it & 1;
        const float* Ah = sm + stage * (STG / 4);
        const float* Bh = Ah + (ABUF / 4);

        #pragma unroll
        for (int ks = 0; ks < 4; ks++) {
            int kp = ks * 8 + 2 * tg;
            float2 af[4][2], bf[4];
            #pragma unroll
            for (int mt = 0; mt < 4; mt++) {
                const float* p = Ah + (wr * 64 + mt * 16 + g) * CW + kp;
                af[mt][0] = *(const float2*)p;
                af[mt][1] = *(const float2*)(p + 8 * CW);
            }
            #pragma unroll
            for (int nt = 0; nt < 4; nt++)
                bf[nt] = *(const float2*)(Bh + (wc * 32 + nt * 8 + g) * CW + kp);
            #pragma unroll
            for (int mt = 0; mt < 4; mt++)
                #pragma unroll
                for (int nt = 0; nt < 4; nt++) {
                    float a[4] = {af[mt][0].x, af[mt][1].x, af[mt][0].y, af[mt][1].y};
                    float b[2] = {bf[nt].x, bf[nt].y};
                    mma8(acc[mt][nt], a, b);
                }
        }

        if ((it & 7) == 7) {
            int colBase = kBase + (it >> 3) * 128 + wc * 32;
            #pragma unroll
            for (int mt = 0; mt < 4; mt++)
                #pragma unroll
                for (int half = 0; half < 2; half++) {
                    int slot = mt * 2 + half;
                    float v[8];
                    #pragma unroll
                    for (int nt = 0; nt < 4; nt++)
                        #pragma unroll
                        for (int j = 0; j < 2; j++)
                            v[nt * 2 + j] = acc[mt][nt][half * 2 + j];
                    // tree max of 8
                    float m01 = fmaxf(v[0], v[1]), m23 = fmaxf(v[2], v[3]);
                    float m45 = fmaxf(v[4], v[5]), m67 = fmaxf(v[6], v[7]);
                    float m03 = fmaxf(m01, m23),   m47 = fmaxf(m45, m67);
                    float m1  = fmaxf(m03, m47);
                    if (m1 > bestV[slot]) {
                        secV[slot] = fmaxf(secV[slot], bestV[slot]);
                        // rare path: find first index + tile second
                        int bi = 0x7fffffff;
                        #pragma unroll
                        for (int q = 0; q < 8; q++)
                            if (v[q] == m1) bi = min(bi, colBase + (q >> 1) * 8 + tg * 2 + (q & 1));
                        float m2 = -INFINITY;
                        #pragma unroll
                        for (int q = 0; q < 8; q++) {
                            int cq = colBase + (q >> 1) * 8 + tg * 2 + (q & 1);
                            m2 = fmaxf(m2, (cq == bi) ? -INFINITY : v[q]);
                        }
                        bestV[slot] = m1;
                        bestI[slot] = bi;
                        secV[slot]  = fmaxf(secV[slot], m2);
                    } else {
                        secV[slot] = fmaxf(secV[slot], m1);
                    }
                }
            #pragma unroll
            for (int mt = 0; mt < 4; mt++)
                #pragma unroll
                for (int nt = 0; nt < 4; nt++)
                    #pragma unroll
                    for (int q = 0; q < 4; q++) acc[mt][nt][q] = 0.0f;
        }
        __syncthreads();
    }

    // cross-thread merge: 16 contributors (wc x tg) per row
    float* sv1 = sm;                   // 2048 floats
    int*   si1 = (int*)(sm + 2048);
    float* sv2 = sm + 4096;
    #pragma unroll
    for (int slot = 0; slot < 8; slot++) {
        int row = wr * 64 + (slot >> 1) * 16 + (slot & 1) * 8 + g;
        int ent = row * 16 + wc * 4 + tg;
        sv1[ent] = bestV[slot];
        si1[ent] = bestI[slot];
        sv2[ent] = secV[slot];
    }
    __syncthreads();
    if (tid < 128) {
        float V1 = -INFINITY, V2 = -INFINITY;
        int I1 = 0x7fffffff;
        #pragma unroll
        for (int t = 0; t < 16; t++) {
            float v1 = sv1[tid * 16 + t];
            int   i1 = si1[tid * 16 + t];
            float v2 = sv2[tid * 16 + t];
            if (v1 > V1 || (v1 == V1 && i1 < I1)) {
                V2 = fmaxf(fmaxf(V2, V1), v2);
                V1 = v1; I1 = i1;
            } else {
                V2 = fmaxf(V2, v1);
            }
        }
        size_t e = (size_t)blockIdx.x * 128 + tid;
        g_pv[e] = make_float2(V1, V2);
        g_pi[e] = I1;
    }
}

// ============================================================================
// Merge slices + rigorous margin test; flag uncertain tokens.
// ============================================================================
__global__ void merge_kernel() {
    int n = blockIdx.x * blockDim.x + threadIdx.x;
    if (n >= NTOK) return;
    int tile = n >> 7, row = n & 127;
    float V1 = -INFINITY, V2 = -INFINITY;
    int I1 = 0x7fffffff;
    #pragma unroll
    for (int s = 0; s < NSLICE; s++) {
        size_t e = ((size_t)(tile * NSLICE + s)) * 128 + row;
        float2 v = g_pv[e];
        int   i1 = g_pi[e];
        if (v.x > V1 || (v.x == V1 && i1 < I1)) {
            V2 = fmaxf(fmaxf(V2, V1), v.y);
            V1 = v.x; I1 = i1;
        } else {
            V2 = fmaxf(V2, v.x);
        }
    }
    float maxBl = __int_as_float(g_maxBlBits);
    float nAh = sqrtf(g_nAh2[n]);
    float nAl = sqrtf(g_nAl2[n]);
    float margin = nAl * 1.0001f + nAh * (maxBl + 5e-5f);
    if (V1 - V2 >= 2.0f * margin) {
        g_idx[n] = I1;
    } else {
        int s = atomicAdd(&g_flagCnt, 1);
        g_flagTok[s] = n;
        g_idx[n] = I1;
    }
}

// ============================================================================
// Exact fp32 rescore over ALL codes for flagged tokens.
// ============================================================================
__global__ __launch_bounds__(256) void rescore_kernel() {
    __shared__ float As[16][128];
    __shared__ float Bs[16][132];
    __shared__ int toks[128];
    int count = g_flagCnt;
    int tile = blockIdx.x >> 3, slice = blockIdx.x & 7;
    int base = tile * 128;
    if (base >= count) return;
    int tid = threadIdx.x;
    if (tid < 128) toks[tid] = (base + tid < count) ? g_flagTok[base + tid] : g_flagTok[0];
    __syncthreads();
    int tx = tid & 15, ty = tid >> 4;
    int kBase = slice * KSLICE;

    float bestV[8];
    int   bestI[8];
    #pragma unroll
    for (int i = 0; i < 8; i++) { bestV[i] = -INFINITY; bestI[i] = 0; }

    for (int k0 = 0; k0 < KSLICE; k0 += 128) {
        float acc[8][8];
        #pragma unroll
        for (int i = 0; i < 8; i++)
            #pragma unroll
            for (int j = 0; j < 8; j++) acc[i][j] = 0.0f;

        for (int d0 = 0; d0 < DD; d0 += 16) {
            __syncthreads();
            #pragma unroll
            for (int i = 0; i < 8; i++) {
                int lin = tid + i * 256;
                int dk = lin >> 7, m = lin & 127;
                size_t o = (size_t)toks[m] * DD + d0 + dk;
                As[dk][m] = g_Ahi[o] + g_Alo[o];
            }
            #pragma unroll
            for (int i = 0; i < 8; i++) {
                int lin = tid + i * 256;
                int kn = lin >> 4, dk = lin & 15;
                size_t o = (size_t)(kBase + k0 + kn) * DD + d0 + dk;
                Bs[dk][kn] = g_Bhi[o] + g_Blo[o];
            }
            __syncthreads();
            #pragma unroll
            for (int dk = 0; dk < 16; dk++) {
                float a[8], bb[8];
                #pragma unroll
                for (int i = 0; i < 8; i++) a[i] = As[dk][ty * 8 + i];
                #pragma unroll
                for (int j = 0; j < 8; j++) bb[j] = Bs[dk][tx * 8 + j];
                #pragma unroll
                for (int i = 0; i < 8; i++)
                    #pragma unroll
                    for (int j = 0; j < 8; j++)
                        acc[i][j] = fmaf(a[i], bb[j], acc[i][j]);
            }
        }
        #pragma unroll
        for (int i = 0; i < 8; i++)
            #pragma unroll
            for (int j = 0; j < 8; j++) {
                float v = acc[i][j];
                if (v > bestV[i]) { bestV[i] = v; bestI[i] = kBase + k0 + tx * 8 + j; }
            }
    }

    __syncthreads();
    float* sv = &As[0][0];
    int*   si = (int*)&Bs[0][0];
    #pragma unroll
    for (int i = 0; i < 8; i++) {
        int m = ty * 8 + i;
        sv[m * 16 + tx] = bestV[i];
        si[m * 16 + tx] = bestI[i];
    }
    __syncthreads();
    if (tid < 128 && base + tid < count) {
        float bv = sv[tid * 16];
        int   bi = si[tid * 16];
        #pragma unroll
        for (int t = 1; t < 16; t++) {
            float v = sv[tid * 16 + t];
            int  id = si[tid * 16 + t];
            if (v > bv || (v == bv && id < bi)) { bv = v; bi = id; }
        }
        g_rv[(size_t)(base + tid) * 8 + slice] = bv;
        g_ri[(size_t)(base + tid) * 8 + slice] = bi;
    }
}

// ============================================================================
// merge2: fold 8 slice partials for flagged tokens
// ============================================================================
__global__ void merge2_kernel() {
    int slot = blockIdx.x * blockDim.x + threadIdx.x;
    if (slot >= g_flagCnt || slot >= NTOK) return;
    float bv = -INFINITY; int bi = 0x7fffffff;
    #pragma unroll
    for (int s = 0; s < 8; s++) {
        float v = g_rv[(size_t)slot * 8 + s];
        int   i = g_ri[(size_t)slot * 8 + s];
        if (v > bv || (v == bv && i < bi)) { bv = v; bi = i; }
    }
    g_idx[g_flagTok[slot]] = bi;
}

// ============================================================================
// finish: EMA scatter + outputs in one z pass
// ============================================================================
__global__ void finish_kernel(const float* __restrict__ z,
                              const float* __restrict__ embedding,
                              float* __restrict__ avg_out,
                              float* __restrict__ cs_out,
                              float* __restrict__ zst,
                              float* __restrict__ zq,
                              float* __restrict__ idxf) {
    int t = blockIdx.x * blockDim.x + threadIdx.x;
    if (t >= ZELEMS) return;
    int hw = t & (HWSZ - 1);
    int bd = t >> 12;
    int d  = bd & (DD - 1);
    int b  = bd >> 8;
    int n  = (b << 12) | hw;
    int id = __ldg(&g_idx[n]);
    float v = z[t];
    atomicAdd(&avg_out[id * DD + d], 0.01f * v);
    float e = __ldg(&embedding[id * DD + d]);
    zq[t]  = e;
    zst[t] = v + (e - v);
    if (d == 0) {
        atomicAdd(&cs_out[id], 0.01f);
        idxf[n] = (float)id;
    }
}

// ============================================================================
extern "C" void kernel_launch(void* const* d_in, const int* in_sizes, int n_in,
                              void* d_out, int out_size) {
    const float* z            = (const float*)d_in[0];
    const float* embedding    = (const float*)d_in[1];
    const float* cluster_size = (const float*)d_in[2];
    const float* embed_avg    = (const float*)d_in[3];

    float* out   = (float*)d_out;
    float* zst_o = out + OFF_ZST;
    float* idx_o = out + OFF_IDX;
    float* zq_o  = out + OFF_ZQ;
    float* emb_o = out + OFF_EMB;
    float* cs_o  = out + OFF_CS;
    float* avg_o = out + OFF_AVG;

    init_kernel<<<(NK * DD + 255) / 256, 256>>>(cluster_size, embed_avg, cs_o, avg_o);

    norm_split_embed<<<NK / 8, 256>>>(embedding);
    transpose_split<<<dim3(HWSZ / 32, DD / 32, 8), dim3(32, 8)>>>(z);

    static bool attr_set = false;
    if (!attr_set) {
        cudaFuncSetAttribute(coarse_gemm,
                             cudaFuncAttributeMaxDynamicSharedMemorySize, GSM);
        attr_set = true;
    }
    coarse_gemm<<<NTILE * NSLICE, 256, GSM>>>();

    merge_kernel<<<NTOK / 256, 256>>>();

    rescore_kernel<<<(NTOK / 128) * 8, 256>>>();

    merge2_kernel<<<NTOK / 256, 256>>>();

    finish_kernel<<<ZELEMS / 256, 256>>>(z, embedding, avg_o, cs_o, zst_o, zq_o, idx_o);

    norm_rows_kernel<<<NK / 8, 256>>>(avg_o, emb_o, NK);
}

// round 6
// speedup vs baseline: 2.5386x; 1.1161x over previous
#include <cuda_runtime.h>
#include <cuda_bf16.h>
#include <math.h>
#include <stdint.h>

// Problem constants
#define NK    8192
#define DD    256
#define NTOK  32768
#define HWSZ  4096
#define ZELEMS 8388608

// Output layout offsets (float32, reference return order)
#define OFF_ZST  0
#define OFF_IDX  8388608
#define OFF_ZQ   8421376
#define OFF_EMB  16809984
#define OFF_CS   18907136
#define OFF_AVG  18915328

#define NSLICE 8
#define KSLICE 1024
#define NTILE64 512       // NTOK / 64

// Scratch (__device__ globals)
__device__ float g_Ahi[NTOK * DD];
__device__ float g_Alo[NTOK * DD];
__device__ float g_Bhi[NK * DD];
__device__ float g_Blo[NK * DD];
__device__ float g_nAh2[NTOK];
__device__ float g_nAl2[NTOK];
__device__ int   g_maxBlBits;
__device__ float2 g_pv[NTILE64 * NSLICE * 64];   // (V1, V2)
__device__ int    g_pi[NTILE64 * NSLICE * 64];   // I1
__device__ int   g_flagCnt;
__device__ int   g_flagTok[NTOK];
__device__ float g_rv[NTOK * 8];
__device__ int   g_ri[NTOK * 8];
__device__ int   g_idx[NTOK];

// ============================================================================
// helpers
// ============================================================================
__device__ __forceinline__ uint32_t smem_to_u32(const void* p) {
    uint32_t a;
    asm("{ .reg .u64 t; cvta.to.shared.u64 t, %1; cvt.u32.u64 %0, t; }" : "=r"(a) : "l"(p));
    return a;
}
__device__ __forceinline__ void cpasync16(uint32_t dst, const void* src) {
    asm volatile("cp.async.cg.shared.global [%0], [%1], 16;" :: "r"(dst), "l"(src));
}
#define CPASYNC_COMMIT() asm volatile("cp.async.commit_group;" ::: "memory")
#define CPASYNC_WAIT(n)  asm volatile("cp.async.wait_group %0;" :: "n"(n) : "memory")

__device__ __forceinline__ float tf32_rna(float x) {
    uint32_t u;
    asm("cvt.rna.tf32.f32 %0, %1;" : "=r"(u) : "f"(x));
    return __uint_as_float(u);
}

__device__ __forceinline__ void mma8(float* c, const float* a, const float* b) {
    asm volatile(
        "mma.sync.aligned.m16n8k8.row.col.f32.tf32.tf32.f32 "
        "{%0,%1,%2,%3}, {%4,%5,%6,%7}, {%8,%9}, {%0,%1,%2,%3};"
        : "+f"(c[0]), "+f"(c[1]), "+f"(c[2]), "+f"(c[3])
        : "r"(__float_as_uint(a[0])), "r"(__float_as_uint(a[1])),
          "r"(__float_as_uint(a[2])), "r"(__float_as_uint(a[3])),
          "r"(__float_as_uint(b[0])), "r"(__float_as_uint(b[1])));
}

// permuted column position within 8-groups: p=(c&3)*2+(c>>2)
__device__ __forceinline__ int dperm(int c) {
    int inner = c & 7;
    return (c & ~7) + ((inner & 3) * 2) + (inner >> 2);
}

// ============================================================================
// init
// ============================================================================
__global__ void init_kernel(const float* __restrict__ cluster_size,
                            const float* __restrict__ embed_avg,
                            float* __restrict__ cs_out,
                            float* __restrict__ avg_out) {
    int t = blockIdx.x * blockDim.x + threadIdx.x;
    if (t < NK) cs_out[t] = 0.99f * cluster_size[t];
    if (t < NK * DD) avg_out[t] = 0.99f * embed_avg[t];
    if (t < NTOK) { g_nAh2[t] = 0.0f; g_nAl2[t] = 0.0f; }
    if (t == 0) { g_maxBlBits = 0; g_flagCnt = 0; }
}

// ============================================================================
// Row L2-normalize (final new_embedding). One warp per row.
// ============================================================================
__global__ void norm_rows_kernel(const float* __restrict__ in,
                                 float* __restrict__ out, int nrows) {
    int warp = (blockIdx.x * blockDim.x + threadIdx.x) >> 5;
    int lane = threadIdx.x & 31;
    if (warp >= nrows) return;
    const float4* ip = reinterpret_cast<const float4*>(in + (size_t)warp * DD);
    float4 v0 = ip[lane];
    float4 v1 = ip[lane + 32];
    float s = v0.x*v0.x + v0.y*v0.y + v0.z*v0.z + v0.w*v0.w
            + v1.x*v1.x + v1.y*v1.y + v1.z*v1.z + v1.w*v1.w;
    #pragma unroll
    for (int off = 16; off > 0; off >>= 1) s += __shfl_xor_sync(0xFFFFFFFFu, s, off);
    float nrm = fmaxf(sqrtf(s), 1e-12f);
    float4 o0, o1;
    o0.x = v0.x/nrm; o0.y = v0.y/nrm; o0.z = v0.z/nrm; o0.w = v0.w/nrm;
    o1.x = v1.x/nrm; o1.y = v1.y/nrm; o1.z = v1.z/nrm; o1.w = v1.w/nrm;
    float4* op = reinterpret_cast<float4*>(out + (size_t)warp * DD);
    op[lane] = o0; op[lane + 32] = o1;
}

// ============================================================================
// normalize codebook rows + exact tf32 split (permuted) + max ||bl||.
// ============================================================================
__global__ void norm_split_embed(const float* __restrict__ in) {
    int warp = (blockIdx.x * blockDim.x + threadIdx.x) >> 5;
    int lane = threadIdx.x & 31;
    if (warp >= NK) return;
    const float4* ip = reinterpret_cast<const float4*>(in + (size_t)warp * DD);
    float4 v0 = ip[lane];
    float4 v1 = ip[lane + 32];
    float s = v0.x*v0.x + v0.y*v0.y + v0.z*v0.z + v0.w*v0.w
            + v1.x*v1.x + v1.y*v1.y + v1.z*v1.z + v1.w*v1.w;
    #pragma unroll
    for (int off = 16; off > 0; off >>= 1) s += __shfl_xor_sync(0xFFFFFFFFu, s, off);
    float inv = 1.0f / fmaxf(sqrtf(s), 1e-12f);
    float vv[8] = {v0.x, v0.y, v0.z, v0.w, v1.x, v1.y, v1.z, v1.w};
    float bl2 = 0.0f;
    #pragma unroll
    for (int i = 0; i < 8; i++) {
        int c = (i < 4) ? (lane * 4 + i) : (128 + lane * 4 + (i - 4));
        float v = vv[i] * inv;
        float h = tf32_rna(v);
        float l = v - h;
        int dp = dperm(c);
        g_Bhi[(size_t)warp * DD + dp] = h;
        g_Blo[(size_t)warp * DD + dp] = l;
        bl2 += l * l;
    }
    #pragma unroll
    for (int off = 16; off > 0; off >>= 1) bl2 += __shfl_xor_sync(0xFFFFFFFFu, bl2, off);
    if (lane == 0) atomicMax(&g_maxBlBits, __float_as_int(sqrtf(bl2)));
}

// ============================================================================
// Transpose z -> token-major, exact tf32 split (permuted), norm accumulation.
// ============================================================================
__global__ void transpose_split(const float* __restrict__ z) {
    __shared__ float t[32][33];
    int tx = threadIdx.x, ty = threadIdx.y;
    int hw0 = blockIdx.x * 32, d0 = blockIdx.y * 32, b = blockIdx.z;
    const float* zb = z + (size_t)b * DD * HWSZ;
    #pragma unroll
    for (int i = 0; i < 4; i++) {
        int d = d0 + ty + i * 8;
        t[ty + i * 8][tx] = zb[(size_t)d * HWSZ + hw0 + tx];
    }
    __syncthreads();
    int dp = d0 + dperm(tx);
    #pragma unroll
    for (int i = 0; i < 4; i++) {
        int hwl = ty + i * 8;
        int n = b * HWSZ + hw0 + hwl;
        float v = t[tx][hwl];
        float h = tf32_rna(v);
        float l = v - h;
        g_Ahi[(size_t)n * DD + dp] = h;
        g_Alo[(size_t)n * DD + dp] = l;
        float hh = h * h, ll = l * l;
        #pragma unroll
        for (int off = 16; off > 0; off >>= 1) {
            hh += __shfl_xor_sync(0xFFFFFFFFu, hh, off);
            ll += __shfl_xor_sync(0xFFFFFFFFu, ll, off);
        }
        if (tx == 0) {
            atomicAdd(&g_nAh2[n], hh);
            atomicAdd(&g_nAl2[n], ll);
        }
    }
}

// ============================================================================
// Coarse GEMM v3: CTA = 64 tokens x 1024 codes, 128 threads (4 warps),
// warptile 64x32, d-chunk 16, 4 CTAs/SM for cross-CTA latency hiding.
// smem row stride 24 words (96B): fragment banks (24g+2tg) conflict-free.
// ============================================================================
#define CW3    24
#define ABUF3  6144            // 64*24*4
#define BBUF3  12288           // 128*24*4
#define STG3   (ABUF3+BBUF3)   // 18432
#define GSM3   (2*STG3)        // 36864

__global__ __launch_bounds__(128, 4) void coarse_gemm() {
    extern __shared__ float sm[];
    const uint32_t sbase = smem_to_u32(sm);
    const int tid  = threadIdx.x;
    const int wc   = tid >> 5;       // warp 0..3 -> 32-col band
    const int lane = tid & 31;
    const int g  = lane >> 2;        // 0..7
    const int tg = lane & 3;         // 0..3

    const int tile    = blockIdx.x >> 3;
    const int slice   = blockIdx.x & 7;
    const int rowBase = tile * 64;
    const int kBase   = slice * KSLICE;

    float acc[4][4][4];
    #pragma unroll
    for (int mt = 0; mt < 4; mt++)
        #pragma unroll
        for (int nt = 0; nt < 4; nt++)
            #pragma unroll
            for (int q = 0; q < 4; q++) acc[mt][nt][q] = 0.0f;

    float bestV[8], secV[8];
    int   bestI[8];
    #pragma unroll
    for (int s = 0; s < 8; s++) {
        bestV[s] = -INFINITY; secV[s] = -INFINITY; bestI[s] = 0x7fffffff;
    }

    // it: 128 iterations = 8 k-tiles x 16 d-chunks (of 16)
    auto load_stage = [&](int it) {
        int stage = it & 1;
        int k0 = kBase + (it >> 4) * 128;
        int d0 = (it & 15) * 16;
        uint32_t sb = sbase + stage * STG3;
        #pragma unroll
        for (int i = 0; i < 6; i++) {
            int ch = tid + i * 128;          // 0..767
            uint32_t dst; const float* src;
            if (ch < 256) {
                int r = ch >> 2, c = ch & 3;
                dst = sb + (uint32_t)(r * 96 + c * 16);
                src = g_Ahi + ((size_t)(rowBase + r) * DD + d0 + c * 4);
            } else {
                int c2 = ch - 256;           // 0..511
                int r = c2 >> 2, c = c2 & 3;
                dst = sb + ABUF3 + (uint32_t)(r * 96 + c * 16);
                src = g_Bhi + ((size_t)(k0 + r) * DD + d0 + c * 4);
            }
            cpasync16(dst, src);
        }
        CPASYNC_COMMIT();
    };

    load_stage(0);

    for (int it = 0; it < 128; it++) {
        if (it + 1 < 128) { load_stage(it + 1); CPASYNC_WAIT(1); }
        else              { CPASYNC_WAIT(0); }
        __syncthreads();

        int stage = it & 1;
        const float* Ah = sm + stage * (STG3 / 4);
        const float* Bh = Ah + (ABUF3 / 4);

        #pragma unroll
        for (int ks = 0; ks < 2; ks++) {
            int kp = ks * 8 + 2 * tg;
            float2 af[4][2], bf[4];
            #pragma unroll
            for (int mt = 0; mt < 4; mt++) {
                const float* p = Ah + (mt * 16 + g) * CW3 + kp;
                af[mt][0] = *(const float2*)p;
                af[mt][1] = *(const float2*)(p + 8 * CW3);
            }
            #pragma unroll
            for (int nt = 0; nt < 4; nt++)
                bf[nt] = *(const float2*)(Bh + (wc * 32 + nt * 8 + g) * CW3 + kp);
            #pragma unroll
            for (int mt = 0; mt < 4; mt++)
                #pragma unroll
                for (int nt = 0; nt < 4; nt++) {
                    float a[4] = {af[mt][0].x, af[mt][1].x, af[mt][0].y, af[mt][1].y};
                    float b[2] = {bf[nt].x, bf[nt].y};
                    mma8(acc[mt][nt], a, b);
                }
        }

        if ((it & 15) == 15) {
            int colBase = kBase + (it >> 4) * 128 + wc * 32;
            #pragma unroll
            for (int mt = 0; mt < 4; mt++)
                #pragma unroll
                for (int half = 0; half < 2; half++) {
                    int slot = mt * 2 + half;
                    float v[8];
                    #pragma unroll
                    for (int nt = 0; nt < 4; nt++)
                        #pragma unroll
                        for (int j = 0; j < 2; j++)
                            v[nt * 2 + j] = acc[mt][nt][half * 2 + j];
                    float m01 = fmaxf(v[0], v[1]), m23 = fmaxf(v[2], v[3]);
                    float m45 = fmaxf(v[4], v[5]), m67 = fmaxf(v[6], v[7]);
                    float m03 = fmaxf(m01, m23),   m47 = fmaxf(m45, m67);
                    float m1  = fmaxf(m03, m47);
                    if (m1 > bestV[slot]) {
                        secV[slot] = fmaxf(secV[slot], bestV[slot]);
                        int bi = 0x7fffffff;
                        #pragma unroll
                        for (int q = 0; q < 8; q++)
                            if (v[q] == m1) bi = min(bi, colBase + (q >> 1) * 8 + tg * 2 + (q & 1));
                        float m2 = -INFINITY;
                        #pragma unroll
                        for (int q = 0; q < 8; q++) {
                            int cq = colBase + (q >> 1) * 8 + tg * 2 + (q & 1);
                            m2 = fmaxf(m2, (cq == bi) ? -INFINITY : v[q]);
                        }
                        bestV[slot] = m1;
                        bestI[slot] = bi;
                        secV[slot]  = fmaxf(secV[slot], m2);
                    } else {
                        secV[slot] = fmaxf(secV[slot], m1);
                    }
                }
            #pragma unroll
            for (int mt = 0; mt < 4; mt++)
                #pragma unroll
                for (int nt = 0; nt < 4; nt++)
                    #pragma unroll
                    for (int q = 0; q < 4; q++) acc[mt][nt][q] = 0.0f;
        }
        __syncthreads();
    }

    // cross-thread merge: 16 contributors (wc x tg) per row, 64 rows
    float* sv1 = sm;                   // 1024 floats
    int*   si1 = (int*)(sm + 1024);
    float* sv2 = sm + 2048;
    #pragma unroll
    for (int slot = 0; slot < 8; slot++) {
        int row = (slot >> 1) * 16 + (slot & 1) * 8 + g;
        int ent = row * 16 + wc * 4 + tg;
        sv1[ent] = bestV[slot];
        si1[ent] = bestI[slot];
        sv2[ent] = secV[slot];
    }
    __syncthreads();
    if (tid < 64) {
        float V1 = -INFINITY, V2 = -INFINITY;
        int I1 = 0x7fffffff;
        #pragma unroll
        for (int t = 0; t < 16; t++) {
            float v1 = sv1[tid * 16 + t];
            int   i1 = si1[tid * 16 + t];
            float v2 = sv2[tid * 16 + t];
            if (v1 > V1 || (v1 == V1 && i1 < I1)) {
                V2 = fmaxf(fmaxf(V2, V1), v2);
                V1 = v1; I1 = i1;
            } else {
                V2 = fmaxf(V2, v1);
            }
        }
        size_t e = (size_t)blockIdx.x * 64 + tid;
        g_pv[e] = make_float2(V1, V2);
        g_pi[e] = I1;
    }
}

// ============================================================================
// Merge slices + rigorous margin test; flag uncertain tokens.
// ============================================================================
__global__ void merge_kernel() {
    int n = blockIdx.x * blockDim.x + threadIdx.x;
    if (n >= NTOK) return;
    int tile = n >> 6, row = n & 63;
    float V1 = -INFINITY, V2 = -INFINITY;
    int I1 = 0x7fffffff;
    #pragma unroll
    for (int s = 0; s < NSLICE; s++) {
        size_t e = ((size_t)(tile * NSLICE + s)) * 64 + row;
        float2 v = g_pv[e];
        int   i1 = g_pi[e];
        if (v.x > V1 || (v.x == V1 && i1 < I1)) {
            V2 = fmaxf(fmaxf(V2, V1), v.y);
            V1 = v.x; I1 = i1;
        } else {
            V2 = fmaxf(V2, v.x);
        }
    }
    float maxBl = __int_as_float(g_maxBlBits);
    float nAh = sqrtf(g_nAh2[n]);
    float nAl = sqrtf(g_nAl2[n]);
    float margin = nAl * 1.0001f + nAh * (maxBl + 5e-5f);
    if (V1 - V2 >= 2.0f * margin) {
        g_idx[n] = I1;
    } else {
        int s = atomicAdd(&g_flagCnt, 1);
        g_flagTok[s] = n;
        g_idx[n] = I1;
    }
}

// ============================================================================
// Exact fp32 rescore: 64-token x 1024-code tiles for balance/occupancy.
// 256 threads, thread-tile 4x8, vectorized smem loads.
// ============================================================================
__global__ __launch_bounds__(256) void rescore_kernel() {
    __shared__ float As[16][68];
    __shared__ float Bs[16][132];
    __shared__ int toks[64];
    int count = g_flagCnt;
    int tile = blockIdx.x >> 3, slice = blockIdx.x & 7;
    int base = tile * 64;
    if (base >= count) return;
    int tid = threadIdx.x;
    if (tid < 64) toks[tid] = (base + tid < count) ? g_flagTok[base + tid] : g_flagTok[0];
    __syncthreads();
    int tx = tid & 15, ty = tid >> 4;   // tx: 8 cols each; ty: 4 rows each
    int kBase = slice * KSLICE;

    float bestV[4];
    int   bestI[4];
    #pragma unroll
    for (int i = 0; i < 4; i++) { bestV[i] = -INFINITY; bestI[i] = 0; }

    for (int k0 = 0; k0 < KSLICE; k0 += 128) {
        float acc[4][8];
        #pragma unroll
        for (int i = 0; i < 4; i++)
            #pragma unroll
            for (int j = 0; j < 8; j++) acc[i][j] = 0.0f;

        for (int d0 = 0; d0 < DD; d0 += 16) {
            __syncthreads();
            // load As: 16x64 = 1024 floats, 4 per thread
            {
                int lin = tid * 4;
                int dk = lin >> 6, m = lin & 63;
                size_t o = (size_t)toks[m] * DD;
                #pragma unroll
                for (int u = 0; u < 4; u++)
                    As[dk][m + u] = g_Ahi[(size_t)toks[m + u] * DD + d0 + dk]
                                  + g_Alo[(size_t)toks[m + u] * DD + d0 + dk];
                (void)o;
            }
            // load Bs: 16x128 = 2048 floats, 8 per thread
            #pragma unroll
            for (int i = 0; i < 8; i++) {
                int lin = tid + i * 256;
                int kn = lin >> 4, dk = lin & 15;
                size_t o = (size_t)(kBase + k0 + kn) * DD + d0 + dk;
                Bs[dk][kn] = g_Bhi[o] + g_Blo[o];
            }
            __syncthreads();
            #pragma unroll
            for (int dk = 0; dk < 16; dk++) {
                float a[4], bb[8];
                #pragma unroll
                for (int i = 0; i < 4; i++) a[i] = As[dk][ty * 4 + i];
                #pragma unroll
                for (int j = 0; j < 8; j++) bb[j] = Bs[dk][tx * 8 + j];
                #pragma unroll
                for (int i = 0; i < 4; i++)
                    #pragma unroll
                    for (int j = 0; j < 8; j++)
                        acc[i][j] = fmaf(a[i], bb[j], acc[i][j]);
            }
        }
        #pragma unroll
        for (int i = 0; i < 4; i++)
            #pragma unroll
            for (int j = 0; j < 8; j++) {
                float v = acc[i][j];
                if (v > bestV[i]) { bestV[i] = v; bestI[i] = kBase + k0 + tx * 8 + j; }
            }
    }

    __syncthreads();
    float* sv = &As[0][0];           // 64*16 = 1024 floats
    int*   si = (int*)&Bs[0][0];
    #pragma unroll
    for (int i = 0; i < 4; i++) {
        int m = ty * 4 + i;
        sv[m * 16 + tx] = bestV[i];
        si[m * 16 + tx] = bestI[i];
    }
    __syncthreads();
    if (tid < 64 && base + tid < count) {
        float bv = sv[tid * 16];
        int   bi = si[tid * 16];
        #pragma unroll
        for (int t = 1; t < 16; t++) {
            float v = sv[tid * 16 + t];
            int  id = si[tid * 16 + t];
            if (v > bv || (v == bv && id < bi)) { bv = v; bi = id; }
        }
        g_rv[(size_t)(base + tid) * 8 + slice] = bv;
        g_ri[(size_t)(base + tid) * 8 + slice] = bi;
    }
}

// ============================================================================
// merge2: fold 8 slice partials for flagged tokens
// ============================================================================
__global__ void merge2_kernel() {
    int slot = blockIdx.x * blockDim.x + threadIdx.x;
    if (slot >= g_flagCnt || slot >= NTOK) return;
    float bv = -INFINITY; int bi = 0x7fffffff;
    #pragma unroll
    for (int s = 0; s < 8; s++) {
        float v = g_rv[(size_t)slot * 8 + s];
        int   i = g_ri[(size_t)slot * 8 + s];
        if (v > bv || (v == bv && i < bi)) { bv = v; bi = i; }
    }
    g_idx[g_flagTok[slot]] = bi;
}

// ============================================================================
// finish: EMA scatter + outputs in one z pass
// ============================================================================
__global__ void finish_kernel(const float* __restrict__ z,
                              const float* __restrict__ embedding,
                              float* __restrict__ avg_out,
                              float* __restrict__ cs_out,
                              float* __restrict__ zst,
                              float* __restrict__ zq,
                              float* __restrict__ idxf) {
    int t = blockIdx.x * blockDim.x + threadIdx.x;
    if (t >= ZELEMS) return;
    int hw = t & (HWSZ - 1);
    int bd = t >> 12;
    int d  = bd & (DD - 1);
    int b  = bd >> 8;
    int n  = (b << 12) | hw;
    int id = __ldg(&g_idx[n]);
    float v = z[t];
    atomicAdd(&avg_out[id * DD + d], 0.01f * v);
    float e = __ldg(&embedding[id * DD + d]);
    zq[t]  = e;
    zst[t] = v + (e - v);
    if (d == 0) {
        atomicAdd(&cs_out[id], 0.01f);
        idxf[n] = (float)id;
    }
}

// ============================================================================
extern "C" void kernel_launch(void* const* d_in, const int* in_sizes, int n_in,
                              void* d_out, int out_size) {
    const float* z            = (const float*)d_in[0];
    const float* embedding    = (const float*)d_in[1];
    const float* cluster_size = (const float*)d_in[2];
    const float* embed_avg    = (const float*)d_in[3];

    float* out   = (float*)d_out;
    float* zst_o = out + OFF_ZST;
    float* idx_o = out + OFF_IDX;
    float* zq_o  = out + OFF_ZQ;
    float* emb_o = out + OFF_EMB;
    float* cs_o  = out + OFF_CS;
    float* avg_o = out + OFF_AVG;

    init_kernel<<<(NK * DD + 255) / 256, 256>>>(cluster_size, embed_avg, cs_o, avg_o);

    norm_split_embed<<<NK / 8, 256>>>(embedding);
    transpose_split<<<dim3(HWSZ / 32, DD / 32, 8), dim3(32, 8)>>>(z);

    static bool attr_set = false;
    if (!attr_set) {
        cudaFuncSetAttribute(coarse_gemm,
                             cudaFuncAttributeMaxDynamicSharedMemorySize, GSM3);
        attr_set = true;
    }
    coarse_gemm<<<NTILE64 * NSLICE, 128, GSM3>>>();

    merge_kernel<<<NTOK / 256, 256>>>();

    rescore_kernel<<<(NTOK / 64) * 8, 256>>>();

    merge2_kernel<<<NTOK / 256, 256>>>();

    finish_kernel<<<ZELEMS / 256, 256>>>(z, embedding, avg_o, cs_o, zst_o, zq_o, idx_o);

    norm_rows_kernel<<<NK / 8, 256>>>(avg_o, emb_o, NK);
}

// round 7
// speedup vs baseline: 3.4162x; 1.3457x over previous
#include <cuda_runtime.h>
#include <cuda_bf16.h>
#include <math.h>
#include <stdint.h>

// Problem constants
#define NK    8192
#define DD    256
#define NTOK  32768
#define HWSZ  4096
#define ZELEMS 8388608

// Output layout offsets (float32, reference return order)
#define OFF_ZST  0
#define OFF_IDX  8388608
#define OFF_ZQ   8421376
#define OFF_EMB  16809984
#define OFF_CS   18907136
#define OFF_AVG  18915328

#define NSLICE 8
#define KSLICE 1024
#define NTILE64 512       // NTOK / 64

// Scratch (__device__ globals)
__device__ float g_Ahi[NTOK * DD];
__device__ float g_Alo[NTOK * DD];
__device__ float g_Bhi[NK * DD];
__device__ float g_Blo[NK * DD];
__device__ float g_nAh2[NTOK];
__device__ float g_nAl2[NTOK];
__device__ int   g_maxBlBits;
__device__ float2 g_pv[NTILE64 * NSLICE * 64];   // (V1, V2)
__device__ int    g_pi[NTILE64 * NSLICE * 64];   // I1
__device__ int   g_flagCnt;
__device__ int   g_flagTok[NTOK];
__device__ float g_rv[NTOK * 8];
__device__ int   g_ri[NTOK * 8];
__device__ int   g_idx[NTOK];

// ============================================================================
// helpers
// ============================================================================
__device__ __forceinline__ uint32_t smem_to_u32(const void* p) {
    uint32_t a;
    asm("{ .reg .u64 t; cvta.to.shared.u64 t, %1; cvt.u32.u64 %0, t; }" : "=r"(a) : "l"(p));
    return a;
}
__device__ __forceinline__ void cpasync16(uint32_t dst, const void* src) {
    asm volatile("cp.async.cg.shared.global [%0], [%1], 16;" :: "r"(dst), "l"(src));
}
#define CPASYNC_COMMIT() asm volatile("cp.async.commit_group;" ::: "memory")
#define CPASYNC_WAIT(n)  asm volatile("cp.async.wait_group %0;" :: "n"(n) : "memory")

__device__ __forceinline__ float tf32_rna(float x) {
    uint32_t u;
    asm("cvt.rna.tf32.f32 %0, %1;" : "=r"(u) : "f"(x));
    return __uint_as_float(u);
}

__device__ __forceinline__ void mma8(float* c, const float* a, const float* b) {
    asm volatile(
        "mma.sync.aligned.m16n8k8.row.col.f32.tf32.tf32.f32 "
        "{%0,%1,%2,%3}, {%4,%5,%6,%7}, {%8,%9}, {%0,%1,%2,%3};"
        : "+f"(c[0]), "+f"(c[1]), "+f"(c[2]), "+f"(c[3])
        : "r"(__float_as_uint(a[0])), "r"(__float_as_uint(a[1])),
          "r"(__float_as_uint(a[2])), "r"(__float_as_uint(a[3])),
          "r"(__float_as_uint(b[0])), "r"(__float_as_uint(b[1])));
}

// permuted column position within 8-groups: p=(c&3)*2+(c>>2)
__device__ __forceinline__ int dperm(int c) {
    int inner = c & 7;
    return (c & ~7) + ((inner & 3) * 2) + (inner >> 2);
}

// ============================================================================
// init
// ============================================================================
__global__ void init_kernel(const float* __restrict__ cluster_size,
                            const float* __restrict__ embed_avg,
                            float* __restrict__ cs_out,
                            float* __restrict__ avg_out) {
    int t = blockIdx.x * blockDim.x + threadIdx.x;
    if (t < NK) cs_out[t] = 0.99f * cluster_size[t];
    if (t < NK * DD) avg_out[t] = 0.99f * embed_avg[t];
    if (t < NTOK) { g_nAh2[t] = 0.0f; g_nAl2[t] = 0.0f; }
    if (t == 0) { g_maxBlBits = 0; g_flagCnt = 0; }
}

// ============================================================================
// Row L2-normalize (final new_embedding). One warp per row.
// ============================================================================
__global__ void norm_rows_kernel(const float* __restrict__ in,
                                 float* __restrict__ out, int nrows) {
    int warp = (blockIdx.x * blockDim.x + threadIdx.x) >> 5;
    int lane = threadIdx.x & 31;
    if (warp >= nrows) return;
    const float4* ip = reinterpret_cast<const float4*>(in + (size_t)warp * DD);
    float4 v0 = ip[lane];
    float4 v1 = ip[lane + 32];
    float s = v0.x*v0.x + v0.y*v0.y + v0.z*v0.z + v0.w*v0.w
            + v1.x*v1.x + v1.y*v1.y + v1.z*v1.z + v1.w*v1.w;
    #pragma unroll
    for (int off = 16; off > 0; off >>= 1) s += __shfl_xor_sync(0xFFFFFFFFu, s, off);
    float nrm = fmaxf(sqrtf(s), 1e-12f);
    float4 o0, o1;
    o0.x = v0.x/nrm; o0.y = v0.y/nrm; o0.z = v0.z/nrm; o0.w = v0.w/nrm;
    o1.x = v1.x/nrm; o1.y = v1.y/nrm; o1.z = v1.z/nrm; o1.w = v1.w/nrm;
    float4* op = reinterpret_cast<float4*>(out + (size_t)warp * DD);
    op[lane] = o0; op[lane + 32] = o1;
}

// ============================================================================
// normalize codebook rows + exact tf32 split (permuted) + max ||bl||.
// ============================================================================
__global__ void norm_split_embed(const float* __restrict__ in) {
    int warp = (blockIdx.x * blockDim.x + threadIdx.x) >> 5;
    int lane = threadIdx.x & 31;
    if (warp >= NK) return;
    const float4* ip = reinterpret_cast<const float4*>(in + (size_t)warp * DD);
    float4 v0 = ip[lane];
    float4 v1 = ip[lane + 32];
    float s = v0.x*v0.x + v0.y*v0.y + v0.z*v0.z + v0.w*v0.w
            + v1.x*v1.x + v1.y*v1.y + v1.z*v1.z + v1.w*v1.w;
    #pragma unroll
    for (int off = 16; off > 0; off >>= 1) s += __shfl_xor_sync(0xFFFFFFFFu, s, off);
    float inv = 1.0f / fmaxf(sqrtf(s), 1e-12f);
    float vv[8] = {v0.x, v0.y, v0.z, v0.w, v1.x, v1.y, v1.z, v1.w};
    float bl2 = 0.0f;
    #pragma unroll
    for (int i = 0; i < 8; i++) {
        int c = (i < 4) ? (lane * 4 + i) : (128 + lane * 4 + (i - 4));
        float v = vv[i] * inv;
        float h = tf32_rna(v);
        float l = v - h;
        int dp = dperm(c);
        g_Bhi[(size_t)warp * DD + dp] = h;
        g_Blo[(size_t)warp * DD + dp] = l;
        bl2 += l * l;
    }
    #pragma unroll
    for (int off = 16; off > 0; off >>= 1) bl2 += __shfl_xor_sync(0xFFFFFFFFu, bl2, off);
    if (lane == 0) atomicMax(&g_maxBlBits, __float_as_int(sqrtf(bl2)));
}

// ============================================================================
// Transpose z -> token-major, exact tf32 split (permuted), norm accumulation.
// ============================================================================
__global__ void transpose_split(const float* __restrict__ z) {
    __shared__ float t[32][33];
    int tx = threadIdx.x, ty = threadIdx.y;
    int hw0 = blockIdx.x * 32, d0 = blockIdx.y * 32, b = blockIdx.z;
    const float* zb = z + (size_t)b * DD * HWSZ;
    #pragma unroll
    for (int i = 0; i < 4; i++) {
        int d = d0 + ty + i * 8;
        t[ty + i * 8][tx] = zb[(size_t)d * HWSZ + hw0 + tx];
    }
    __syncthreads();
    int dp = d0 + dperm(tx);
    #pragma unroll
    for (int i = 0; i < 4; i++) {
        int hwl = ty + i * 8;
        int n = b * HWSZ + hw0 + hwl;
        float v = t[tx][hwl];
        float h = tf32_rna(v);
        float l = v - h;
        g_Ahi[(size_t)n * DD + dp] = h;
        g_Alo[(size_t)n * DD + dp] = l;
        float hh = h * h, ll = l * l;
        #pragma unroll
        for (int off = 16; off > 0; off >>= 1) {
            hh += __shfl_xor_sync(0xFFFFFFFFu, hh, off);
            ll += __shfl_xor_sync(0xFFFFFFFFu, ll, off);
        }
        if (tx == 0) {
            atomicAdd(&g_nAh2[n], hh);
            atomicAdd(&g_nAl2[n], ll);
        }
    }
}

// ============================================================================
// Coarse GEMM v4: 64 tok x 1024 codes, 128 thr, warptile 64x32, 4 CTAs/SM.
// 3-stage cp.async pipeline, ONE __syncthreads per iter, pointer-increment
// addressing (no per-iter address recompute).
// ============================================================================
#define CW3    24
#define ABUF3  6144            // 64*24*4
#define BBUF3  12288           // 128*24*4
#define STG3   (ABUF3+BBUF3)   // 18432
#define GSM4   (3*STG3)        // 55296

__global__ __launch_bounds__(128, 4) void coarse_gemm() {
    extern __shared__ float sm[];
    const uint32_t sbase = smem_to_u32(sm);
    const int tid  = threadIdx.x;
    const int wc   = tid >> 5;
    const int lane = tid & 31;
    const int g  = lane >> 2;
    const int tg = lane & 3;

    const int tile    = blockIdx.x >> 3;
    const int slice   = blockIdx.x & 7;
    const int rowBase = tile * 64;
    const int kBase   = slice * KSLICE;

    float acc[4][4][4];
    #pragma unroll
    for (int mt = 0; mt < 4; mt++)
        #pragma unroll
        for (int nt = 0; nt < 4; nt++)
            #pragma unroll
            for (int q = 0; q < 4; q++) acc[mt][nt][q] = 0.0f;

    float bestV[8], secV[8];
    int   bestI[8];
    #pragma unroll
    for (int s = 0; s < 8; s++) {
        bestV[s] = -INFINITY; secV[s] = -INFINITY; bestI[s] = 0x7fffffff;
    }

    // per-thread load chunks: A rows rA,rA+32 ; B rows rA+32*jj
    const int rA = tid >> 2;
    const int cA = tid & 3;
    const float* pA[2];
    const float* pB[4];
    uint32_t offA[2], offB[4];
    #pragma unroll
    for (int j = 0; j < 2; j++) {
        pA[j]   = g_Ahi + ((size_t)(rowBase + rA + 32 * j) * DD + cA * 4);
        offA[j] = (uint32_t)((rA + 32 * j) * 96 + cA * 16);
    }
    #pragma unroll
    for (int j = 0; j < 4; j++) {
        pB[j]   = g_Bhi + ((size_t)(kBase + rA + 32 * j) * DD + cA * 4);
        offB[j] = (uint32_t)(ABUF3 + (rA + 32 * j) * 96 + cA * 16);
    }
    int ldj = 0;
    auto load = [&](uint32_t sb) {
        cpasync16(sb + offA[0], pA[0]);
        cpasync16(sb + offA[1], pA[1]);
        #pragma unroll
        for (int j = 0; j < 4; j++) cpasync16(sb + offB[j], pB[j]);
        CPASYNC_COMMIT();
        int wrap = ((ldj & 15) == 15);
        ldj++;
        int dA = wrap ? (16 - 256) : 16;
        int dB = wrap ? (16 - 256 + 128 * DD) : 16;
        pA[0] += dA; pA[1] += dA;
        #pragma unroll
        for (int j = 0; j < 4; j++) pB[j] += dB;
    };

    const uint32_t stB0 = sbase, stB1 = sbase + STG3, stB2 = sbase + 2 * STG3;
    load(stB0); load(stB1);
    CPASYNC_WAIT(1);
    __syncthreads();

    int stg = 0;
    uint32_t stNext = stB2;
    for (int it = 0; it < 128; it++) {
        if (it < 126) load(stNext);

        const float* Ah = sm + stg * (STG3 / 4);
        const float* Bh = Ah + (ABUF3 / 4);

        #pragma unroll
        for (int ks = 0; ks < 2; ks++) {
            int kp = ks * 8 + 2 * tg;
            float2 af[4][2], bf[4];
            #pragma unroll
            for (int mt = 0; mt < 4; mt++) {
                const float* p = Ah + (mt * 16 + g) * CW3 + kp;
                af[mt][0] = *(const float2*)p;
                af[mt][1] = *(const float2*)(p + 8 * CW3);
            }
            #pragma unroll
            for (int nt = 0; nt < 4; nt++)
                bf[nt] = *(const float2*)(Bh + (wc * 32 + nt * 8 + g) * CW3 + kp);
            #pragma unroll
            for (int mt = 0; mt < 4; mt++)
                #pragma unroll
                for (int nt = 0; nt < 4; nt++) {
                    float a[4] = {af[mt][0].x, af[mt][1].x, af[mt][0].y, af[mt][1].y};
                    float b[2] = {bf[nt].x, bf[nt].y};
                    mma8(acc[mt][nt], a, b);
                }
        }

        if ((it & 15) == 15) {
            int colBase = kBase + (it >> 4) * 128 + wc * 32;
            #pragma unroll
            for (int mt = 0; mt < 4; mt++)
                #pragma unroll
                for (int half = 0; half < 2; half++) {
                    int slot = mt * 2 + half;
                    float v[8];
                    #pragma unroll
                    for (int nt = 0; nt < 4; nt++)
                        #pragma unroll
                        for (int j = 0; j < 2; j++)
                            v[nt * 2 + j] = acc[mt][nt][half * 2 + j];
                    float m01 = fmaxf(v[0], v[1]), m23 = fmaxf(v[2], v[3]);
                    float m45 = fmaxf(v[4], v[5]), m67 = fmaxf(v[6], v[7]);
                    float m03 = fmaxf(m01, m23),   m47 = fmaxf(m45, m67);
                    float m1  = fmaxf(m03, m47);
                    if (m1 > bestV[slot]) {
                        secV[slot] = fmaxf(secV[slot], bestV[slot]);
                        int bi = 0x7fffffff;
                        #pragma unroll
                        for (int q = 0; q < 8; q++)
                            if (v[q] == m1) bi = min(bi, colBase + (q >> 1) * 8 + tg * 2 + (q & 1));
                        float m2 = -INFINITY;
                        #pragma unroll
                        for (int q = 0; q < 8; q++) {
                            int cq = colBase + (q >> 1) * 8 + tg * 2 + (q & 1);
                            m2 = fmaxf(m2, (cq == bi) ? -INFINITY : v[q]);
                        }
                        bestV[slot] = m1;
                        bestI[slot] = bi;
                        secV[slot]  = fmaxf(secV[slot], m2);
                    } else {
                        secV[slot] = fmaxf(secV[slot], m1);
                    }
                }
            #pragma unroll
            for (int mt = 0; mt < 4; mt++)
                #pragma unroll
                for (int nt = 0; nt < 4; nt++)
                    #pragma unroll
                    for (int q = 0; q < 4; q++) acc[mt][nt][q] = 0.0f;
        }

        if (it < 126) CPASYNC_WAIT(1);
        else          CPASYNC_WAIT(0);
        __syncthreads();

        stg++; if (stg == 3) stg = 0;
        stNext += STG3; if (stNext > stB2) stNext = stB0;
    }

    // cross-thread merge: 16 contributors (wc x tg) per row, 64 rows
    float* sv1 = sm;
    int*   si1 = (int*)(sm + 1024);
    float* sv2 = sm + 2048;
    #pragma unroll
    for (int slot = 0; slot < 8; slot++) {
        int row = (slot >> 1) * 16 + (slot & 1) * 8 + g;
        int ent = row * 16 + wc * 4 + tg;
        sv1[ent] = bestV[slot];
        si1[ent] = bestI[slot];
        sv2[ent] = secV[slot];
    }
    __syncthreads();
    if (tid < 64) {
        float V1 = -INFINITY, V2 = -INFINITY;
        int I1 = 0x7fffffff;
        #pragma unroll
        for (int t = 0; t < 16; t++) {
            float v1 = sv1[tid * 16 + t];
            int   i1 = si1[tid * 16 + t];
            float v2 = sv2[tid * 16 + t];
            if (v1 > V1 || (v1 == V1 && i1 < I1)) {
                V2 = fmaxf(fmaxf(V2, V1), v2);
                V1 = v1; I1 = i1;
            } else {
                V2 = fmaxf(V2, v1);
            }
        }
        size_t e = (size_t)blockIdx.x * 64 + tid;
        g_pv[e] = make_float2(V1, V2);
        g_pi[e] = I1;
    }
}

// ============================================================================
// Merge slices + rigorous margin test; flag uncertain tokens.
// ============================================================================
__global__ void merge_kernel() {
    int n = blockIdx.x * blockDim.x + threadIdx.x;
    if (n >= NTOK) return;
    int tile = n >> 6, row = n & 63;
    float V1 = -INFINITY, V2 = -INFINITY;
    int I1 = 0x7fffffff;
    #pragma unroll
    for (int s = 0; s < NSLICE; s++) {
        size_t e = ((size_t)(tile * NSLICE + s)) * 64 + row;
        float2 v = g_pv[e];
        int   i1 = g_pi[e];
        if (v.x > V1 || (v.x == V1 && i1 < I1)) {
            V2 = fmaxf(fmaxf(V2, V1), v.y);
            V1 = v.x; I1 = i1;
        } else {
            V2 = fmaxf(V2, v.x);
        }
    }
    float maxBl = __int_as_float(g_maxBlBits);
    float nAh = sqrtf(g_nAh2[n]);
    float nAl = sqrtf(g_nAl2[n]);
    float margin = nAl * 1.0001f + nAh * (maxBl + 5e-5f);
    if (V1 - V2 >= 2.0f * margin) {
        g_idx[n] = I1;
    } else {
        int s = atomicAdd(&g_flagCnt, 1);
        g_flagTok[s] = n;
        g_idx[n] = I1;
    }
}

// ============================================================================
// 3xTF32 tensor-core rescore for flagged tokens (R3-proven precision).
// 64 flagged tokens x 1024 codes per CTA; warptile 64x32; argmax epilogue.
// ============================================================================
#define RABUF  6144                 // Ah 64x24x4 (Al at +RABUF)
#define RBOFF  (2*RABUF)            // 12288: Bh base (Bl at +BBUF3)
#define RSTG   (2*RABUF + 2*BBUF3)  // 36864
#define RGSM   (2*RSTG)             // 73728

__global__ __launch_bounds__(128, 2) void rescore_mma() {
    extern __shared__ float sm[];
    const uint32_t sbase = smem_to_u32(sm);
    __shared__ int toks[64];
    int count = g_flagCnt;
    const int tile  = blockIdx.x >> 3;
    const int slice = blockIdx.x & 7;
    const int base  = tile * 64;
    if (base >= count) return;
    const int tid  = threadIdx.x;
    const int wc   = tid >> 5;
    const int lane = tid & 31;
    const int g  = lane >> 2;
    const int tg = lane & 3;
    const int kBase = slice * KSLICE;

    if (tid < 64) toks[tid] = (base + tid < count) ? g_flagTok[base + tid] : g_flagTok[0];
    __syncthreads();

    const ptrdiff_t ALO = g_Alo - g_Ahi;
    const ptrdiff_t BLO = g_Blo - g_Bhi;

    const int rA = tid >> 2;
    const int cA = tid & 3;
    const float* pA[2];
    const float* pB[4];
    uint32_t offA[2], offB[4];
    #pragma unroll
    for (int j = 0; j < 2; j++) {
        pA[j]   = g_Ahi + ((size_t)toks[rA + 32 * j] * DD + cA * 4);
        offA[j] = (uint32_t)((rA + 32 * j) * 96 + cA * 16);
    }
    #pragma unroll
    for (int j = 0; j < 4; j++) {
        pB[j]   = g_Bhi + ((size_t)(kBase + rA + 32 * j) * DD + cA * 4);
        offB[j] = (uint32_t)(RBOFF + (rA + 32 * j) * 96 + cA * 16);
    }
    int ldj = 0;
    auto load = [&](uint32_t sb) {
        #pragma unroll
        for (int j = 0; j < 2; j++) {
            cpasync16(sb + offA[j],         pA[j]);
            cpasync16(sb + offA[j] + RABUF, pA[j] + ALO);
        }
        #pragma unroll
        for (int j = 0; j < 4; j++) {
            cpasync16(sb + offB[j],         pB[j]);
            cpasync16(sb + offB[j] + BBUF3, pB[j] + BLO);
        }
        CPASYNC_COMMIT();
        int wrap = ((ldj & 15) == 15);
        ldj++;
        int dA = wrap ? (16 - 256) : 16;
        int dB = wrap ? (16 - 256 + 128 * DD) : 16;
        pA[0] += dA; pA[1] += dA;
        #pragma unroll
        for (int j = 0; j < 4; j++) pB[j] += dB;
    };

    float acc[4][4][4];
    #pragma unroll
    for (int mt = 0; mt < 4; mt++)
        #pragma unroll
        for (int nt = 0; nt < 4; nt++)
            #pragma unroll
            for (int q = 0; q < 4; q++) acc[mt][nt][q] = 0.0f;

    float bestV[8];
    int   bestI[8];
    #pragma unroll
    for (int s = 0; s < 8; s++) { bestV[s] = -INFINITY; bestI[s] = 0x7fffffff; }

    load(sbase);
    CPASYNC_WAIT(0);
    __syncthreads();

    for (int it = 0; it < 128; it++) {
        int stg = it & 1;
        if (it < 127) load(sbase + ((it + 1) & 1) * RSTG);

        const float* Ah = sm + stg * (RSTG / 4);
        const float* Al = Ah + (RABUF / 4);
        const float* Bh = Ah + (RBOFF / 4);
        const float* Bl = Bh + (BBUF3 / 4);

        #pragma unroll
        for (int ks = 0; ks < 2; ks++) {
            int kp = ks * 8 + 2 * tg;
            float2 ah[4][2], al[4][2], bh[4], bl[4];
            #pragma unroll
            for (int mt = 0; mt < 4; mt++) {
                int ro = (mt * 16 + g) * CW3 + kp;
                ah[mt][0] = *(const float2*)(Ah + ro);
                ah[mt][1] = *(const float2*)(Ah + ro + 8 * CW3);
                al[mt][0] = *(const float2*)(Al + ro);
                al[mt][1] = *(const float2*)(Al + ro + 8 * CW3);
            }
            #pragma unroll
            for (int nt = 0; nt < 4; nt++) {
                int co = (wc * 32 + nt * 8 + g) * CW3 + kp;
                bh[nt] = *(const float2*)(Bh + co);
                bl[nt] = *(const float2*)(Bl + co);
            }
            #pragma unroll
            for (int mt = 0; mt < 4; mt++)
                #pragma unroll
                for (int nt = 0; nt < 4; nt++) {
                    float ahr[4] = {ah[mt][0].x, ah[mt][1].x, ah[mt][0].y, ah[mt][1].y};
                    float alr[4] = {al[mt][0].x, al[mt][1].x, al[mt][0].y, al[mt][1].y};
                    float bhr[2] = {bh[nt].x, bh[nt].y};
                    float blr[2] = {bl[nt].x, bl[nt].y};
                    mma8(acc[mt][nt], ahr, bhr);
                    mma8(acc[mt][nt], ahr, blr);
                    mma8(acc[mt][nt], alr, bhr);
                }
        }

        if ((it & 15) == 15) {
            int colBase = kBase + (it >> 4) * 128 + wc * 32;
            #pragma unroll
            for (int mt = 0; mt < 4; mt++)
                #pragma unroll
                for (int half = 0; half < 2; half++) {
                    int slot = mt * 2 + half;
                    float v[8];
                    #pragma unroll
                    for (int nt = 0; nt < 4; nt++)
                        #pragma unroll
                        for (int j = 0; j < 2; j++)
                            v[nt * 2 + j] = acc[mt][nt][half * 2 + j];
                    float m01 = fmaxf(v[0], v[1]), m23 = fmaxf(v[2], v[3]);
                    float m45 = fmaxf(v[4], v[5]), m67 = fmaxf(v[6], v[7]);
                    float m1  = fmaxf(fmaxf(m01, m23), fmaxf(m45, m67));
                    if (m1 > bestV[slot]) {
                        int bi = 0x7fffffff;
                        #pragma unroll
                        for (int q = 0; q < 8; q++)
                            if (v[q] == m1) bi = min(bi, colBase + (q >> 1) * 8 + tg * 2 + (q & 1));
                        bestV[slot] = m1;
                        bestI[slot] = bi;
                    }
                }
            #pragma unroll
            for (int mt = 0; mt < 4; mt++)
                #pragma unroll
                for (int nt = 0; nt < 4; nt++)
                    #pragma unroll
                    for (int q = 0; q < 4; q++) acc[mt][nt][q] = 0.0f;
        }

        CPASYNC_WAIT(0);
        __syncthreads();
    }

    // cross-thread merge: 16 contributors per row, 64 rows
    float* sv = sm;
    int*   si = (int*)(sm + 1024);
    #pragma unroll
    for (int slot = 0; slot < 8; slot++) {
        int row = (slot >> 1) * 16 + (slot & 1) * 8 + g;
        int ent = row * 16 + wc * 4 + tg;
        sv[ent] = bestV[slot];
        si[ent] = bestI[slot];
    }
    __syncthreads();
    if (tid < 64 && base + tid < count) {
        float bv = sv[tid * 16];
        int   bi = si[tid * 16];
        #pragma unroll
        for (int t = 1; t < 16; t++) {
            float v = sv[tid * 16 + t];
            int  id = si[tid * 16 + t];
            if (v > bv || (v == bv && id < bi)) { bv = v; bi = id; }
        }
        g_rv[(size_t)(base + tid) * 8 + slice] = bv;
        g_ri[(size_t)(base + tid) * 8 + slice] = bi;
    }
}

// ============================================================================
// merge2: fold 8 slice partials for flagged tokens
// ============================================================================
__global__ void merge2_kernel() {
    int slot = blockIdx.x * blockDim.x + threadIdx.x;
    if (slot >= g_flagCnt || slot >= NTOK) return;
    float bv = -INFINITY; int bi = 0x7fffffff;
    #pragma unroll
    for (int s = 0; s < 8; s++) {
        float v = g_rv[(size_t)slot * 8 + s];
        int   i = g_ri[(size_t)slot * 8 + s];
        if (v > bv || (v == bv && i < bi)) { bv = v; bi = i; }
    }
    g_idx[g_flagTok[slot]] = bi;
}

// ============================================================================
// finish: EMA scatter + outputs in one z pass
// ============================================================================
__global__ void finish_kernel(const float* __restrict__ z,
                              const float* __restrict__ embedding,
                              float* __restrict__ avg_out,
                              float* __restrict__ cs_out,
                              float* __restrict__ zst,
                              float* __restrict__ zq,
                              float* __restrict__ idxf) {
    int t = blockIdx.x * blockDim.x + threadIdx.x;
    if (t >= ZELEMS) return;
    int hw = t & (HWSZ - 1);
    int bd = t >> 12;
    int d  = bd & (DD - 1);
    int b  = bd >> 8;
    int n  = (b << 12) | hw;
    int id = __ldg(&g_idx[n]);
    float v = z[t];
    atomicAdd(&avg_out[id * DD + d], 0.01f * v);
    float e = __ldg(&embedding[id * DD + d]);
    zq[t]  = e;
    zst[t] = v + (e - v);
    if (d == 0) {
        atomicAdd(&cs_out[id], 0.01f);
        idxf[n] = (float)id;
    }
}

// ============================================================================
extern "C" void kernel_launch(void* const* d_in, const int* in_sizes, int n_in,
                              void* d_out, int out_size) {
    const float* z            = (const float*)d_in[0];
    const float* embedding    = (const float*)d_in[1];
    const float* cluster_size = (const float*)d_in[2];
    const float* embed_avg    = (const float*)d_in[3];

    float* out   = (float*)d_out;
    float* zst_o = out + OFF_ZST;
    float* idx_o = out + OFF_IDX;
    float* zq_o  = out + OFF_ZQ;
    float* emb_o = out + OFF_EMB;
    float* cs_o  = out + OFF_CS;
    float* avg_o = out + OFF_AVG;

    init_kernel<<<(NK * DD + 255) / 256, 256>>>(cluster_size, embed_avg, cs_o, avg_o);

    norm_split_embed<<<NK / 8, 256>>>(embedding);
    transpose_split<<<dim3(HWSZ / 32, DD / 32, 8), dim3(32, 8)>>>(z);

    static bool attr_set = false;
    if (!attr_set) {
        cudaFuncSetAttribute(coarse_gemm,
                             cudaFuncAttributeMaxDynamicSharedMemorySize, GSM4);
        cudaFuncSetAttribute(rescore_mma,
                             cudaFuncAttributeMaxDynamicSharedMemorySize, RGSM);
        attr_set = true;
    }
    coarse_gemm<<<NTILE64 * NSLICE, 128, GSM4>>>();

    merge_kernel<<<NTOK / 256, 256>>>();

    rescore_mma<<<(NTOK / 64) * 8, 128, RGSM>>>();

    merge2_kernel<<<NTOK / 256, 256>>>();

    finish_kernel<<<ZELEMS / 256, 256>>>(z, embedding, avg_o, cs_o, zst_o, zq_o, idx_o);

    norm_rows_kernel<<<NK / 8, 256>>>(avg_o, emb_o, NK);
}